// round 13
// baseline (speedup 1.0000x reference)
#include <cuda_runtime.h>
#include <cuda_fp16.h>
#include <mma.h>
#include <math.h>
#include <stdint.h>

using namespace nvcuda;

#define Bdim 2
#define Lq 8192
#define Edim 1024
#define Hn 16
#define Dh 64
#define Cch 256
#define Nch (Lq / Cch)            // 32
#define BL (Bdim * Lq)            // 16384
#define NCHUNKS (Bdim * Hn * Nch) // 1024

// ---------------- scratch (device globals: no allocation allowed) ----------
__device__ float g_q[BL * Edim];
__device__ float g_k[BL * Edim];
__device__ float g_v[BL * Edim];
__device__ float g_y[BL * Edim];
__device__ float g_Sc[NCHUNKS * Dh * Dh];
__device__ float g_Sp[NCHUNKS * Dh * Dh];
__device__ float g_zc[NCHUNKS * Dh];
__device__ float g_zp[NCHUNKS * Dh];

// fp16 hi/lo operands (referenced only from device code)
__device__ __half g_xh[BL * Edim];
__device__ __half g_xl[BL * Edim];
__device__ __half g_ath[BL * Edim];
__device__ __half g_atl[BL * Edim];
__device__ __half g_wh[4][Edim * Edim];
__device__ __half g_wl[4][Edim * Edim];

// ============================ helpers =======================================
__device__ __forceinline__ uint32_t p6_smem_u32(const void* p) {
    uint32_t a;
    asm("{ .reg .u64 t; cvta.to.shared.u64 t, %1; cvt.u32.u64 %0, t; }"
        : "=r"(a) : "l"(p));
    return a;
}

#define CP_ASYNC_16(dst, src) \
    asm volatile("cp.async.cg.shared.global [%0], [%1], 16;" \
        :: "r"(dst), "l"(src))
#define CP_ASYNC_COMMIT() asm volatile("cp.async.commit_group;" ::: "memory")
#define CP_ASYNC_WAIT_1() asm volatile("cp.async.wait_group 1;" ::: "memory")
#define CP_ASYNC_WAIT_0() asm volatile("cp.async.wait_group 0;" ::: "memory")

__device__ __forceinline__ void p6_split1(float v, __half& h, __half& l) {
    h = __float2half_rn(v);
    l = __float2half_rn(__fsub_rn(v, __half2float(h)));
}

// ============================ split kernels =================================
__global__ void __launch_bounds__(256) p6_split_x_kernel(const float* __restrict__ x)
{
    size_t i = ((size_t)blockIdx.x * 256 + threadIdx.x) * 8;
    float4 v0 = *(const float4*)(x + i);
    float4 v1 = *(const float4*)(x + i + 4);
    float a[8] = {v0.x, v0.y, v0.z, v0.w, v1.x, v1.y, v1.z, v1.w};
    __half2 h[4], l[4];
#pragma unroll
    for (int j = 0; j < 4; j++) {
        __half hx, hy, lx, ly;
        p6_split1(a[2 * j], hx, lx);
        p6_split1(a[2 * j + 1], hy, ly);
        h[j] = __halves2half2(hx, hy);
        l[j] = __halves2half2(lx, ly);
    }
    *(float4*)(g_xh + i) = *(float4*)h;
    *(float4*)(g_xl + i) = *(float4*)l;
}

__global__ void __launch_bounds__(256) p6_split_w_kernel(
    const float* __restrict__ W0, const float* __restrict__ W1,
    const float* __restrict__ W2, const float* __restrict__ W3)
{
    int z = blockIdx.y;
    const float* W = (z == 0) ? W0 : (z == 1) ? W1 : (z == 2) ? W2 : W3;
    size_t i = ((size_t)blockIdx.x * 256 + threadIdx.x) * 8;
    float4 v0 = *(const float4*)(W + i);
    float4 v1 = *(const float4*)(W + i + 4);
    float a[8] = {v0.x, v0.y, v0.z, v0.w, v1.x, v1.y, v1.z, v1.w};
    __half2 h[4], l[4];
#pragma unroll
    for (int j = 0; j < 4; j++) {
        __half hx, hy, lx, ly;
        p6_split1(a[2 * j], hx, lx);
        p6_split1(a[2 * j + 1], hy, ly);
        h[j] = __halves2half2(hx, hy);
        l[j] = __halves2half2(lx, ly);
    }
    *(float4*)(&g_wh[z][0] + i) = *(float4*)h;
    *(float4*)(&g_wl[z][0] + i) = *(float4*)l;
}

// ============================ pure-FP16x3 WMMA GEMM (BK=16) =================
// D = A @ W, compensated AhWh + AhWl + AlWh, operands pre-split fp16.
// mma loop pass-interleaved: dependent mmas separated by independent ones.
#define NKTp (Edim / 16)       // 64 k-blocks
#define LDAH 24
#define LDBH 136
#define AH_O 0
#define AL_O (128 * LDAH)
#define BH_O (2 * 128 * LDAH)
#define BL_O (BH_O + 16 * LDBH)
#define STG_H (2 * 128 * LDAH + 2 * 16 * LDBH)   // 10496 halfs
#define GSMB 65536

template <int ACT, int OSEL, int AISEL, int WIDX>
__global__ void __launch_bounds__(256, 2) p6_gemm_kernel(
    const float* __restrict__ bias, const float* __restrict__ resid)
{
    extern __shared__ __half smh[];
    uint32_t sbase = p6_smem_u32(smh);
    int tid = threadIdx.x;
    int lane = tid & 31, wid = tid >> 5;

    const __half* Ahg = (AISEL == 0) ? &g_xh[0] : &g_ath[0];
    const __half* Alg = (AISEL == 0) ? &g_xl[0] : &g_atl[0];
    const __half* Bhg = &g_wh[WIDX][0];
    const __half* Blg = &g_wl[WIDX][0];
    float* Cout = (OSEL == 0) ? &g_q[0] : (OSEL == 1) ? &g_k[0]
                : (OSEL == 2) ? &g_v[0] : &g_y[0];

    int bm = blockIdx.y * 128;
    int bn = blockIdx.x * 128;

    int arow = tid >> 1, acol = (tid & 1) * 8;
    int brow = tid >> 4, bcol = (tid & 15) * 8;
    const __half* gAh = Ahg + (size_t)(bm + arow) * Edim + acol;
    const __half* gAl = Alg + (size_t)(bm + arow) * Edim + acol;
    const __half* gBh = Bhg + (size_t)brow * Edim + bn + bcol;
    const __half* gBl = Blg + (size_t)brow * Edim + bn + bcol;
    uint32_t a_dst = (uint32_t)(arow * LDAH + acol) * 2;
    uint32_t b_dst = (uint32_t)(brow * LDBH + bcol) * 2;

#define ISSUE_LOADS(kt, stg) do {                                          \
    uint32_t s0 = sbase + (uint32_t)(stg) * (STG_H * 2);                   \
    size_t ao = (size_t)(kt) * 16;                                         \
    size_t bo = (size_t)(kt) * 16 * Edim;                                  \
    CP_ASYNC_16(s0 + AH_O * 2 + a_dst, gAh + ao);                          \
    CP_ASYNC_16(s0 + AL_O * 2 + a_dst, gAl + ao);                          \
    CP_ASYNC_16(s0 + BH_O * 2 + b_dst, gBh + bo);                          \
    CP_ASYNC_16(s0 + BL_O * 2 + b_dst, gBl + bo);                          \
    CP_ASYNC_COMMIT();                                                      \
} while (0)

    int Mb = (wid & 1) * 64;
    int Nb = (wid >> 1) * 32;

    wmma::fragment<wmma::accumulator, 16, 16, 16, float> acc[4][2];
#pragma unroll
    for (int mt = 0; mt < 4; mt++)
#pragma unroll
        for (int nt = 0; nt < 2; nt++) wmma::fill_fragment(acc[mt][nt], 0.0f);

    ISSUE_LOADS(0, 0);

    for (int kt = 0; kt < NKTp; kt++) {
        if (kt + 1 < NKTp) {
            ISSUE_LOADS(kt + 1, (kt + 1) & 1);
            CP_ASYNC_WAIT_1();
        } else {
            CP_ASYNC_WAIT_0();
        }
        __syncthreads();

        const __half* st = smh + (uint32_t)(kt & 1) * STG_H;

        // hoist B fragments (loaded once per k-block)
        wmma::fragment<wmma::matrix_b, 16, 16, 16, __half, wmma::row_major> fbh[2], fbl[2];
#pragma unroll
        for (int nt = 0; nt < 2; nt++) {
            wmma::load_matrix_sync(fbh[nt], st + BH_O + Nb + nt * 16, LDBH);
            wmma::load_matrix_sync(fbl[nt], st + BL_O + Nb + nt * 16, LDBH);
        }
#pragma unroll
        for (int mt = 0; mt < 4; mt++) {
            wmma::fragment<wmma::matrix_a, 16, 16, 16, __half, wmma::row_major> fah, fal;
            wmma::load_matrix_sync(fah, st + AH_O + (Mb + mt * 16) * LDAH, LDAH);
            wmma::load_matrix_sync(fal, st + AL_O + (Mb + mt * 16) * LDAH, LDAH);
            // pass-interleaved: dependent mmas separated by the other nt
            wmma::mma_sync(acc[mt][0], fah, fbl[0], acc[mt][0]);
            wmma::mma_sync(acc[mt][1], fah, fbl[1], acc[mt][1]);
            wmma::mma_sync(acc[mt][0], fal, fbh[0], acc[mt][0]);
            wmma::mma_sync(acc[mt][1], fal, fbh[1], acc[mt][1]);
            wmma::mma_sync(acc[mt][0], fah, fbh[0], acc[mt][0]);
            wmma::mma_sync(acc[mt][1], fah, fbh[1], acc[mt][1]);
        }
        __syncthreads();
    }

    // ---- epilogue: per-warp 64x32 f32 smem staging ----
    float* wst = (float*)smh + wid * (64 * 32);
#pragma unroll
    for (int mt = 0; mt < 4; mt++)
#pragma unroll
        for (int nt = 0; nt < 2; nt++)
            wmma::store_matrix_sync(wst + mt * 16 * 32 + nt * 16, acc[mt][nt],
                                    32, wmma::mem_row_major);
    __syncwarp();

    for (int e = lane; e < 64 * 8; e += 32) {
        int r = e >> 3, cb = (e & 7) * 4;
        float4 v = *(float4*)(wst + r * 32 + cb);
        int grow = bm + Mb + r;
        int gcol = bn + Nb + cb;
        float4 bb = *(const float4*)&bias[gcol];
        v.x += bb.x; v.y += bb.y; v.z += bb.z; v.w += bb.w;
        if (ACT == 1) {
            v.x = v.x > 0.f ? v.x + 1.f : expf(v.x);
            v.y = v.y > 0.f ? v.y + 1.f : expf(v.y);
            v.z = v.z > 0.f ? v.z + 1.f : expf(v.z);
            v.w = v.w > 0.f ? v.w + 1.f : expf(v.w);
        }
        if (ACT == 2) {
            float4 xr = *(const float4*)&resid[(size_t)grow * Edim + gcol];
            v.x += xr.x; v.y += xr.y; v.z += xr.z; v.w += xr.w;
        }
        *(float4*)&Cout[(size_t)grow * Edim + gcol] = v;
    }
#undef ISSUE_LOADS
}

// ---------------- per-chunk KV stats (proven) --------------------------------
__global__ void __launch_bounds__(512) p6_chunk_stats_kernel()
{
    __shared__ float ks[64][64];
    __shared__ float vs[64][64];
    int blk = blockIdx.x;
    int n = blk % Nch;
    int h = (blk / Nch) % Hn;
    int b = blk / (Nch * Hn);
    int rowbase = b * Lq + n * Cch;
    int colbase = h * Dh;
    int t = threadIdx.x;
    int d = t >> 3;
    int e0 = (t & 7) * 8;

    float acc[8];
#pragma unroll
    for (int j = 0; j < 8; j++) acc[j] = 0.f;
    float zacc = 0.f;

    for (int st = 0; st < Cch; st += 64) {
        for (int i = t; i < 1024; i += 512) {
            int r = i >> 4, c4 = (i & 15) * 4;
            size_t gofs = (size_t)(rowbase + st + r) * Edim + colbase + c4;
            *(float4*)&ks[r][c4] = *(const float4*)&g_k[gofs];
            *(float4*)&vs[r][c4] = *(const float4*)&g_v[gofs];
        }
        __syncthreads();
#pragma unroll 4
        for (int s = 0; s < 64; s++) {
            float kd = ks[s][d];
            float4 v0 = *(const float4*)&vs[s][e0];
            float4 v1 = *(const float4*)&vs[s][e0 + 4];
            acc[0] += kd * v0.x; acc[1] += kd * v0.y;
            acc[2] += kd * v0.z; acc[3] += kd * v0.w;
            acc[4] += kd * v1.x; acc[5] += kd * v1.y;
            acc[6] += kd * v1.z; acc[7] += kd * v1.w;
            zacc += kd;
        }
        __syncthreads();
    }

    float* Sb = &g_Sc[(size_t)blk * (Dh * Dh) + d * 64 + e0];
    float4 o0, o1;
    o0.x = acc[0]; o0.y = acc[1]; o0.z = acc[2]; o0.w = acc[3];
    o1.x = acc[4]; o1.y = acc[5]; o1.z = acc[6]; o1.w = acc[7];
    *(float4*)(Sb + 0) = o0;
    *(float4*)(Sb + 4) = o1;
    if ((t & 7) == 0) g_zc[blk * Dh + d] = zacc;
}

// ---------------- exclusive prefix scan over chunks per (b,h) ---------------
__global__ void __launch_bounds__(256) p6_scan_kernel()
{
    int bh = blockIdx.x;
    int t = threadIdx.x;
    float run[16];
#pragma unroll
    for (int i = 0; i < 16; i++) run[i] = 0.f;
    float zrun = 0.f;

    for (int n = 0; n < Nch; n++) {
        size_t base = ((size_t)bh * Nch + n) * (Dh * Dh);
#pragma unroll
        for (int i = 0; i < 16; i++) {
            int idx = t + i * 256;
            g_Sp[base + idx] = run[i];
            run[i] += g_Sc[base + idx];
        }
        if (t < Dh) {
            size_t zb = ((size_t)bh * Nch + n) * Dh + t;
            g_zp[zb] = zrun;
            zrun += g_zc[zb];
        }
    }
}

// ---------------- per-chunk attention output (proven) ------------------------
__global__ void __launch_bounds__(128) p6_chunk_out_kernel()
{
    __shared__ float ks[64][64];
    __shared__ float vs[64][64];
    int bid = blockIdx.x;
    int blk = bid >> 1;
    int rh = bid & 1;
    int n = blk % Nch;
    int h = (blk / Nch) % Hn;
    int b = blk / (Nch * Hn);
    int rowbase = b * Lq + n * Cch;
    int colbase = h * Dh;
    int t = threadIdx.x;
    int row = rh * 128 + t;

    const float* qrow = &g_q[(size_t)(rowbase + row) * Edim + colbase];

    float qv[64];
#pragma unroll
    for (int j = 0; j < 16; j++) {
        float4 qq = *(const float4*)(qrow + 4 * j);
        qv[4 * j + 0] = qq.x; qv[4 * j + 1] = qq.y;
        qv[4 * j + 2] = qq.z; qv[4 * j + 3] = qq.w;
    }

    float acc[64];
#pragma unroll
    for (int j = 0; j < 64; j++) acc[j] = 0.f;

    const float* Sb = &g_Sp[(size_t)blk * (Dh * Dh)];
    for (int d = 0; d < 64; d++) {
        float qd = __ldg(qrow + d);
        const float4* S4 = (const float4*)(Sb + d * 64);
#pragma unroll
        for (int j = 0; j < 16; j++) {
            float4 sv = __ldg(S4 + j);
            acc[4 * j + 0] += qd * sv.x;
            acc[4 * j + 1] += qd * sv.y;
            acc[4 * j + 2] += qd * sv.z;
            acc[4 * j + 3] += qd * sv.w;
        }
    }

    float den = 0.f;
    const float* zb = &g_zp[(size_t)blk * Dh];
#pragma unroll
    for (int j = 0; j < 16; j++) {
        den += qv[4 * j + 0] * __ldg(zb + 4 * j + 0);
        den += qv[4 * j + 1] * __ldg(zb + 4 * j + 1);
        den += qv[4 * j + 2] * __ldg(zb + 4 * j + 2);
        den += qv[4 * j + 3] * __ldg(zb + 4 * j + 3);
    }

    int st_limit = (rh + 1) * 128;
    for (int st = 0; st < st_limit; st += 64) {
        for (int i = t; i < 1024; i += 128) {
            int r = i >> 4, c4 = (i & 15) * 4;
            size_t gofs = (size_t)(rowbase + st + r) * Edim + colbase + c4;
            *(float4*)&ks[r][c4] = *(const float4*)&g_k[gofs];
            *(float4*)&vs[r][c4] = *(const float4*)&g_v[gofs];
        }
        __syncthreads();
        int smax = row - st + 1;
        if (smax > 64) smax = 64;
        for (int s = 0; s < smax; s++) {
            const float4* k4 = (const float4*)&ks[s][0];
            float dot = 0.f;
#pragma unroll
            for (int j = 0; j < 16; j++) {
                float4 kk = k4[j];
                dot += qv[4 * j + 0] * kk.x + qv[4 * j + 1] * kk.y
                     + qv[4 * j + 2] * kk.z + qv[4 * j + 3] * kk.w;
            }
            den += dot;
            const float4* v4 = (const float4*)&vs[s][0];
#pragma unroll
            for (int j = 0; j < 16; j++) {
                float4 vv = v4[j];
                acc[4 * j + 0] += dot * vv.x;
                acc[4 * j + 1] += dot * vv.y;
                acc[4 * j + 2] += dot * vv.z;
                acc[4 * j + 3] += dot * vv.w;
            }
        }
        __syncthreads();
    }

    float inv = 1.0f / (den + 1e-6f);
    size_t oofs = (size_t)(rowbase + row) * Edim + colbase;
#pragma unroll
    for (int j = 0; j < 16; j++) {
        float o0 = acc[4 * j + 0] * inv;
        float o1 = acc[4 * j + 1] * inv;
        float o2 = acc[4 * j + 2] * inv;
        float o3 = acc[4 * j + 3] * inv;
        __half h0, h1, h2, h3, l0, l1, l2, l3;
        p6_split1(o0, h0, l0);
        p6_split1(o1, h1, l1);
        p6_split1(o2, h2, l2);
        p6_split1(o3, h3, l3);
        __half2 hh[2] = {__halves2half2(h0, h1), __halves2half2(h2, h3)};
        __half2 ll[2] = {__halves2half2(l0, l1), __halves2half2(l2, l3)};
        *(float2*)(g_ath + oofs + 4 * j) = *(float2*)hh;
        *(float2*)(g_atl + oofs + 4 * j) = *(float2*)ll;
    }
}

// ---------------- LayerNorm --------------------------------------------------
__global__ void __launch_bounds__(256) p6_ln_kernel(
    const float* __restrict__ gamma, const float* __restrict__ beta,
    float* __restrict__ out)
{
    int row = blockIdx.x;
    int t = threadIdx.x;
    const float* yr = &g_y[(size_t)row * Edim];
    float4 v = *(const float4*)(yr + t * 4);
    float s = v.x + v.y + v.z + v.w;
    float ss = v.x * v.x + v.y * v.y + v.z * v.z + v.w * v.w;
#pragma unroll
    for (int o = 16; o; o >>= 1) {
        s += __shfl_down_sync(0xffffffffu, s, o);
        ss += __shfl_down_sync(0xffffffffu, ss, o);
    }
    __shared__ float sh_s[8], sh_ss[8];
    int w = t >> 5, ln = t & 31;
    if (ln == 0) { sh_s[w] = s; sh_ss[w] = ss; }
    __syncthreads();
    if (t == 0) {
        float a = 0.f, b2 = 0.f;
#pragma unroll
        for (int i = 0; i < 8; i++) { a += sh_s[i]; b2 += sh_ss[i]; }
        sh_s[0] = a; sh_ss[0] = b2;
    }
    __syncthreads();
    float mu = sh_s[0] * (1.0f / Edim);
    float var = sh_ss[0] * (1.0f / Edim) - mu * mu;
    float rstd = rsqrtf(var + 1e-5f);
    float4 g = *(const float4*)(gamma + t * 4);
    float4 bb = *(const float4*)(beta + t * 4);
    float4 o;
    o.x = g.x * (v.x - mu) * rstd + bb.x;
    o.y = g.y * (v.y - mu) * rstd + bb.y;
    o.z = g.z * (v.z - mu) * rstd + bb.z;
    o.w = g.w * (v.w - mu) * rstd + bb.w;
    *(float4*)(out + (size_t)row * Edim + t * 4) = o;
}

// ---------------- launch ------------------------------------------------------
extern "C" void kernel_launch(void* const* d_in, const int* in_sizes, int n_in,
                              void* d_out, int out_size)
{
    const float* x     = (const float*)d_in[0];
    const float* Wq    = (const float*)d_in[1];
    const float* bq    = (const float*)d_in[2];
    const float* Wk    = (const float*)d_in[3];
    const float* bk    = (const float*)d_in[4];
    const float* Wv    = (const float*)d_in[5];
    const float* bv    = (const float*)d_in[6];
    const float* Wo    = (const float*)d_in[7];
    const float* bo    = (const float*)d_in[8];
    const float* gamma = (const float*)d_in[9];
    const float* beta  = (const float*)d_in[10];
    float* out = (float*)d_out;

    cudaFuncSetAttribute(p6_gemm_kernel<1, 0, 0, 0>, cudaFuncAttributeMaxDynamicSharedMemorySize, GSMB);
    cudaFuncSetAttribute(p6_gemm_kernel<1, 1, 0, 1>, cudaFuncAttributeMaxDynamicSharedMemorySize, GSMB);
    cudaFuncSetAttribute(p6_gemm_kernel<0, 2, 0, 2>, cudaFuncAttributeMaxDynamicSharedMemorySize, GSMB);
    cudaFuncSetAttribute(p6_gemm_kernel<2, 3, 1, 3>, cudaFuncAttributeMaxDynamicSharedMemorySize, GSMB);

    dim3 ggrid(Edim / 128, BL / 128);
    dim3 wgrid(Edim * Edim / (256 * 8), 4);

    p6_split_x_kernel<<<BL * Edim / (256 * 8), 256>>>(x);
    p6_split_w_kernel<<<wgrid, 256>>>(Wq, Wk, Wv, Wo);

    p6_gemm_kernel<1, 0, 0, 0><<<ggrid, 256, GSMB>>>(bq, nullptr);   // q
    p6_gemm_kernel<1, 1, 0, 1><<<ggrid, 256, GSMB>>>(bk, nullptr);   // k
    p6_gemm_kernel<0, 2, 0, 2><<<ggrid, 256, GSMB>>>(bv, nullptr);   // v

    p6_chunk_stats_kernel<<<NCHUNKS, 512>>>();
    p6_scan_kernel<<<Bdim * Hn, 256>>>();
    p6_chunk_out_kernel<<<NCHUNKS * 2, 128>>>();

    p6_gemm_kernel<2, 3, 1, 3><<<ggrid, 256, GSMB>>>(bo, x);         // y

    p6_ln_kernel<<<BL, 256>>>(gamma, beta, out);
}

// round 14
// speedup vs baseline: 1.0435x; 1.0435x over previous
#include <cuda_runtime.h>
#include <cuda_fp16.h>
#include <mma.h>
#include <math.h>
#include <stdint.h>

using namespace nvcuda;

#define Bdim 2
#define Lq 8192
#define Edim 1024
#define Hn 16
#define Dh 64
#define Cch 256
#define Nch (Lq / Cch)            // 32
#define BL (Bdim * Lq)            // 16384
#define NCHUNKS (Bdim * Hn * Nch) // 1024

// ---------------- scratch (device globals: no allocation allowed) ----------
__device__ float g_q[BL * Edim];
__device__ float g_k[BL * Edim];
__device__ float g_v[BL * Edim];
__device__ float g_y[BL * Edim];
__device__ float g_Sc[NCHUNKS * Dh * Dh];
__device__ float g_Sp[NCHUNKS * Dh * Dh];
__device__ float g_zc[NCHUNKS * Dh];
__device__ float g_zp[NCHUNKS * Dh];

// fp16 hi/lo operands (referenced only from device code)
__device__ __half g_xh[BL * Edim];
__device__ __half g_xl[BL * Edim];
__device__ __half g_ath[BL * Edim];
__device__ __half g_atl[BL * Edim];
__device__ __half g_wh[4][Edim * Edim];
__device__ __half g_wl[4][Edim * Edim];

// ============================ helpers =======================================
__device__ __forceinline__ uint32_t p7_smem_u32(const void* p) {
    uint32_t a;
    asm("{ .reg .u64 t; cvta.to.shared.u64 t, %1; cvt.u32.u64 %0, t; }"
        : "=r"(a) : "l"(p));
    return a;
}

#define CP_ASYNC_16(dst, src) \
    asm volatile("cp.async.cg.shared.global [%0], [%1], 16;" \
        :: "r"(dst), "l"(src))
#define CP_ASYNC_COMMIT() asm volatile("cp.async.commit_group;" ::: "memory")
#define CP_ASYNC_WAIT_1() asm volatile("cp.async.wait_group 1;" ::: "memory")
#define CP_ASYNC_WAIT_0() asm volatile("cp.async.wait_group 0;" ::: "memory")

__device__ __forceinline__ void p7_split1(float v, __half& h, __half& l) {
    h = __float2half_rn(v);
    l = __float2half_rn(__fsub_rn(v, __half2float(h)));
}

// ============================ split kernels =================================
__global__ void __launch_bounds__(256) p7_split_x_kernel(const float* __restrict__ x)
{
    size_t i = ((size_t)blockIdx.x * 256 + threadIdx.x) * 8;
    float4 v0 = *(const float4*)(x + i);
    float4 v1 = *(const float4*)(x + i + 4);
    float a[8] = {v0.x, v0.y, v0.z, v0.w, v1.x, v1.y, v1.z, v1.w};
    __half2 h[4], l[4];
#pragma unroll
    for (int j = 0; j < 4; j++) {
        __half hx, hy, lx, ly;
        p7_split1(a[2 * j], hx, lx);
        p7_split1(a[2 * j + 1], hy, ly);
        h[j] = __halves2half2(hx, hy);
        l[j] = __halves2half2(lx, ly);
    }
    *(float4*)(g_xh + i) = *(float4*)h;
    *(float4*)(g_xl + i) = *(float4*)l;
}

__global__ void __launch_bounds__(256) p7_split_w_kernel(
    const float* __restrict__ W0, const float* __restrict__ W1,
    const float* __restrict__ W2, const float* __restrict__ W3)
{
    int z = blockIdx.y;
    const float* W = (z == 0) ? W0 : (z == 1) ? W1 : (z == 2) ? W2 : W3;
    size_t i = ((size_t)blockIdx.x * 256 + threadIdx.x) * 8;
    float4 v0 = *(const float4*)(W + i);
    float4 v1 = *(const float4*)(W + i + 4);
    float a[8] = {v0.x, v0.y, v0.z, v0.w, v1.x, v1.y, v1.z, v1.w};
    __half2 h[4], l[4];
#pragma unroll
    for (int j = 0; j < 4; j++) {
        __half hx, hy, lx, ly;
        p7_split1(a[2 * j], hx, lx);
        p7_split1(a[2 * j + 1], hy, ly);
        h[j] = __halves2half2(hx, hy);
        l[j] = __halves2half2(lx, ly);
    }
    *(float4*)(&g_wh[z][0] + i) = *(float4*)h;
    *(float4*)(&g_wl[z][0] + i) = *(float4*)l;
}

// ============================ pure-FP16x3 WMMA GEMM (R11 proven body) =======
// MODE 0: fused qkv — blockIdx.z = widx (0:q phi, 1:k phi, 2:v none), A = x halves
// MODE 1: output GEMM — widx=3, A = attn halves, ACT = +resid
#define NKTp (Edim / 16)       // 64 k-blocks
#define LDAH 24
#define LDBH 136
#define AH_O 0
#define AL_O (128 * LDAH)
#define BH_O (2 * 128 * LDAH)
#define BL_O (BH_O + 16 * LDBH)
#define STG_H (2 * 128 * LDAH + 2 * 16 * LDBH)   // 10496 halfs
#define GSMB 65536

template <int MODE>
__global__ void __launch_bounds__(256, 2) p7_gemm_kernel(
    const float* __restrict__ bias0, const float* __restrict__ bias1,
    const float* __restrict__ bias2, const float* __restrict__ resid)
{
    extern __shared__ __half smh[];
    uint32_t sbase = p7_smem_u32(smh);
    int tid = threadIdx.x;
    int lane = tid & 31, wid = tid >> 5;

    int widx = (MODE == 0) ? blockIdx.z : 3;
    const __half* Ahg = (MODE == 0) ? &g_xh[0] : &g_ath[0];
    const __half* Alg = (MODE == 0) ? &g_xl[0] : &g_atl[0];
    const __half* Bhg = &g_wh[widx][0];
    const __half* Blg = &g_wl[widx][0];
    float* Cout;
    const float* bias;
    if (MODE == 0) {
        Cout = (widx == 0) ? &g_q[0] : (widx == 1) ? &g_k[0] : &g_v[0];
        bias = (widx == 0) ? bias0 : (widx == 1) ? bias1 : bias2;
    } else {
        Cout = &g_y[0];
        bias = bias0;
    }

    int bm = blockIdx.y * 128;
    int bn = blockIdx.x * 128;

    int arow = tid >> 1, acol = (tid & 1) * 8;
    int brow = tid >> 4, bcol = (tid & 15) * 8;
    const __half* gAh = Ahg + (size_t)(bm + arow) * Edim + acol;
    const __half* gAl = Alg + (size_t)(bm + arow) * Edim + acol;
    const __half* gBh = Bhg + (size_t)brow * Edim + bn + bcol;
    const __half* gBl = Blg + (size_t)brow * Edim + bn + bcol;
    uint32_t a_dst = (uint32_t)(arow * LDAH + acol) * 2;
    uint32_t b_dst = (uint32_t)(brow * LDBH + bcol) * 2;

#define ISSUE_LOADS(kt, stg) do {                                          \
    uint32_t s0 = sbase + (uint32_t)(stg) * (STG_H * 2);                   \
    size_t ao = (size_t)(kt) * 16;                                         \
    size_t bo = (size_t)(kt) * 16 * Edim;                                  \
    CP_ASYNC_16(s0 + AH_O * 2 + a_dst, gAh + ao);                          \
    CP_ASYNC_16(s0 + AL_O * 2 + a_dst, gAl + ao);                          \
    CP_ASYNC_16(s0 + BH_O * 2 + b_dst, gBh + bo);                          \
    CP_ASYNC_16(s0 + BL_O * 2 + b_dst, gBl + bo);                          \
    CP_ASYNC_COMMIT();                                                      \
} while (0)

    int Mb = (wid & 1) * 64;
    int Nb = (wid >> 1) * 32;

    wmma::fragment<wmma::accumulator, 16, 16, 16, float> acc[4][2];
#pragma unroll
    for (int mt = 0; mt < 4; mt++)
#pragma unroll
        for (int nt = 0; nt < 2; nt++) wmma::fill_fragment(acc[mt][nt], 0.0f);

    ISSUE_LOADS(0, 0);

    for (int kt = 0; kt < NKTp; kt++) {
        if (kt + 1 < NKTp) {
            ISSUE_LOADS(kt + 1, (kt + 1) & 1);
            CP_ASYNC_WAIT_1();
        } else {
            CP_ASYNC_WAIT_0();
        }
        __syncthreads();   // stage kt visible

        const __half* st = smh + (uint32_t)(kt & 1) * STG_H;
#pragma unroll
        for (int nt = 0; nt < 2; nt++) {
            wmma::fragment<wmma::matrix_b, 16, 16, 16, __half, wmma::row_major> fbh, fbl;
            wmma::load_matrix_sync(fbh, st + BH_O + Nb + nt * 16, LDBH);
            wmma::load_matrix_sync(fbl, st + BL_O + Nb + nt * 16, LDBH);
#pragma unroll
            for (int mt = 0; mt < 4; mt++) {
                wmma::fragment<wmma::matrix_a, 16, 16, 16, __half, wmma::row_major> fah, fal;
                wmma::load_matrix_sync(fah, st + AH_O + (Mb + mt * 16) * LDAH, LDAH);
                wmma::load_matrix_sync(fal, st + AL_O + (Mb + mt * 16) * LDAH, LDAH);
                wmma::mma_sync(acc[mt][nt], fah, fbl, acc[mt][nt]);
                wmma::mma_sync(acc[mt][nt], fal, fbh, acc[mt][nt]);
                wmma::mma_sync(acc[mt][nt], fah, fbh, acc[mt][nt]);
            }
        }
        __syncthreads();   // all reads done before buffer reuse
    }

    // ---- epilogue: per-warp 64x32 f32 smem staging ----
    float* wst = (float*)smh + wid * (64 * 32);
#pragma unroll
    for (int mt = 0; mt < 4; mt++)
#pragma unroll
        for (int nt = 0; nt < 2; nt++)
            wmma::store_matrix_sync(wst + mt * 16 * 32 + nt * 16, acc[mt][nt],
                                    32, wmma::mem_row_major);
    __syncwarp();

    bool do_phi = (MODE == 0) && (widx != 2);
    for (int e = lane; e < 64 * 8; e += 32) {
        int r = e >> 3, cb = (e & 7) * 4;
        float4 v = *(float4*)(wst + r * 32 + cb);
        int grow = bm + Mb + r;
        int gcol = bn + Nb + cb;
        float4 bb = *(const float4*)&bias[gcol];
        v.x += bb.x; v.y += bb.y; v.z += bb.z; v.w += bb.w;
        if (do_phi) {
            v.x = v.x > 0.f ? v.x + 1.f : expf(v.x);
            v.y = v.y > 0.f ? v.y + 1.f : expf(v.y);
            v.z = v.z > 0.f ? v.z + 1.f : expf(v.z);
            v.w = v.w > 0.f ? v.w + 1.f : expf(v.w);
        }
        if (MODE == 1) {
            float4 xr = *(const float4*)&resid[(size_t)grow * Edim + gcol];
            v.x += xr.x; v.y += xr.y; v.z += xr.z; v.w += xr.w;
        }
        *(float4*)&Cout[(size_t)grow * Edim + gcol] = v;
    }
#undef ISSUE_LOADS
}

// ---------------- per-chunk KV stats (proven) --------------------------------
__global__ void __launch_bounds__(512) p7_chunk_stats_kernel()
{
    __shared__ float ks[64][64];
    __shared__ float vs[64][64];
    int blk = blockIdx.x;
    int n = blk % Nch;
    int h = (blk / Nch) % Hn;
    int b = blk / (Nch * Hn);
    int rowbase = b * Lq + n * Cch;
    int colbase = h * Dh;
    int t = threadIdx.x;
    int d = t >> 3;
    int e0 = (t & 7) * 8;

    float acc[8];
#pragma unroll
    for (int j = 0; j < 8; j++) acc[j] = 0.f;
    float zacc = 0.f;

    for (int st = 0; st < Cch; st += 64) {
        for (int i = t; i < 1024; i += 512) {
            int r = i >> 4, c4 = (i & 15) * 4;
            size_t gofs = (size_t)(rowbase + st + r) * Edim + colbase + c4;
            *(float4*)&ks[r][c4] = *(const float4*)&g_k[gofs];
            *(float4*)&vs[r][c4] = *(const float4*)&g_v[gofs];
        }
        __syncthreads();
#pragma unroll 4
        for (int s = 0; s < 64; s++) {
            float kd = ks[s][d];
            float4 v0 = *(const float4*)&vs[s][e0];
            float4 v1 = *(const float4*)&vs[s][e0 + 4];
            acc[0] += kd * v0.x; acc[1] += kd * v0.y;
            acc[2] += kd * v0.z; acc[3] += kd * v0.w;
            acc[4] += kd * v1.x; acc[5] += kd * v1.y;
            acc[6] += kd * v1.z; acc[7] += kd * v1.w;
            zacc += kd;
        }
        __syncthreads();
    }

    float* Sb = &g_Sc[(size_t)blk * (Dh * Dh) + d * 64 + e0];
    float4 o0, o1;
    o0.x = acc[0]; o0.y = acc[1]; o0.z = acc[2]; o0.w = acc[3];
    o1.x = acc[4]; o1.y = acc[5]; o1.z = acc[6]; o1.w = acc[7];
    *(float4*)(Sb + 0) = o0;
    *(float4*)(Sb + 4) = o1;
    if ((t & 7) == 0) g_zc[blk * Dh + d] = zacc;
}

// ---------------- exclusive prefix scan over chunks per (b,h) ---------------
__global__ void __launch_bounds__(256) p7_scan_kernel()
{
    int bh = blockIdx.x;
    int t = threadIdx.x;
    float run[16];
#pragma unroll
    for (int i = 0; i < 16; i++) run[i] = 0.f;
    float zrun = 0.f;

    for (int n = 0; n < Nch; n++) {
        size_t base = ((size_t)bh * Nch + n) * (Dh * Dh);
#pragma unroll
        for (int i = 0; i < 16; i++) {
            int idx = t + i * 256;
            g_Sp[base + idx] = run[i];
            run[i] += g_Sc[base + idx];
        }
        if (t < Dh) {
            size_t zb = ((size_t)bh * Nch + n) * Dh + t;
            g_zp[zb] = zrun;
            zrun += g_zc[zb];
        }
    }
}

// ---------------- per-chunk attention output (proven) ------------------------
__global__ void __launch_bounds__(128) p7_chunk_out_kernel()
{
    __shared__ float ks[64][64];
    __shared__ float vs[64][64];
    int bid = blockIdx.x;
    int blk = bid >> 1;
    int rh = bid & 1;
    int n = blk % Nch;
    int h = (blk / Nch) % Hn;
    int b = blk / (Nch * Hn);
    int rowbase = b * Lq + n * Cch;
    int colbase = h * Dh;
    int t = threadIdx.x;
    int row = rh * 128 + t;

    const float* qrow = &g_q[(size_t)(rowbase + row) * Edim + colbase];

    float qv[64];
#pragma unroll
    for (int j = 0; j < 16; j++) {
        float4 qq = *(const float4*)(qrow + 4 * j);
        qv[4 * j + 0] = qq.x; qv[4 * j + 1] = qq.y;
        qv[4 * j + 2] = qq.z; qv[4 * j + 3] = qq.w;
    }

    float acc[64];
#pragma unroll
    for (int j = 0; j < 64; j++) acc[j] = 0.f;

    const float* Sb = &g_Sp[(size_t)blk * (Dh * Dh)];
    for (int d = 0; d < 64; d++) {
        float qd = __ldg(qrow + d);
        const float4* S4 = (const float4*)(Sb + d * 64);
#pragma unroll
        for (int j = 0; j < 16; j++) {
            float4 sv = __ldg(S4 + j);
            acc[4 * j + 0] += qd * sv.x;
            acc[4 * j + 1] += qd * sv.y;
            acc[4 * j + 2] += qd * sv.z;
            acc[4 * j + 3] += qd * sv.w;
        }
    }

    float den = 0.f;
    const float* zb = &g_zp[(size_t)blk * Dh];
#pragma unroll
    for (int j = 0; j < 16; j++) {
        den += qv[4 * j + 0] * __ldg(zb + 4 * j + 0);
        den += qv[4 * j + 1] * __ldg(zb + 4 * j + 1);
        den += qv[4 * j + 2] * __ldg(zb + 4 * j + 2);
        den += qv[4 * j + 3] * __ldg(zb + 4 * j + 3);
    }

    int st_limit = (rh + 1) * 128;
    for (int st = 0; st < st_limit; st += 64) {
        for (int i = t; i < 1024; i += 128) {
            int r = i >> 4, c4 = (i & 15) * 4;
            size_t gofs = (size_t)(rowbase + st + r) * Edim + colbase + c4;
            *(float4*)&ks[r][c4] = *(const float4*)&g_k[gofs];
            *(float4*)&vs[r][c4] = *(const float4*)&g_v[gofs];
        }
        __syncthreads();
        int smax = row - st + 1;
        if (smax > 64) smax = 64;
        for (int s = 0; s < smax; s++) {
            const float4* k4 = (const float4*)&ks[s][0];
            float dot = 0.f;
#pragma unroll
            for (int j = 0; j < 16; j++) {
                float4 kk = k4[j];
                dot += qv[4 * j + 0] * kk.x + qv[4 * j + 1] * kk.y
                     + qv[4 * j + 2] * kk.z + qv[4 * j + 3] * kk.w;
            }
            den += dot;
            const float4* v4 = (const float4*)&vs[s][0];
#pragma unroll
            for (int j = 0; j < 16; j++) {
                float4 vv = v4[j];
                acc[4 * j + 0] += dot * vv.x;
                acc[4 * j + 1] += dot * vv.y;
                acc[4 * j + 2] += dot * vv.z;
                acc[4 * j + 3] += dot * vv.w;
            }
        }
        __syncthreads();
    }

    float inv = 1.0f / (den + 1e-6f);
    size_t oofs = (size_t)(rowbase + row) * Edim + colbase;
#pragma unroll
    for (int j = 0; j < 16; j++) {
        float o0 = acc[4 * j + 0] * inv;
        float o1 = acc[4 * j + 1] * inv;
        float o2 = acc[4 * j + 2] * inv;
        float o3 = acc[4 * j + 3] * inv;
        __half h0, h1, h2, h3, l0, l1, l2, l3;
        p7_split1(o0, h0, l0);
        p7_split1(o1, h1, l1);
        p7_split1(o2, h2, l2);
        p7_split1(o3, h3, l3);
        __half2 hh[2] = {__halves2half2(h0, h1), __halves2half2(h2, h3)};
        __half2 ll[2] = {__halves2half2(l0, l1), __halves2half2(l2, l3)};
        *(float2*)(g_ath + oofs + 4 * j) = *(float2*)hh;
        *(float2*)(g_atl + oofs + 4 * j) = *(float2*)ll;
    }
}

// ---------------- LayerNorm --------------------------------------------------
__global__ void __launch_bounds__(256) p7_ln_kernel(
    const float* __restrict__ gamma, const float* __restrict__ beta,
    float* __restrict__ out)
{
    int row = blockIdx.x;
    int t = threadIdx.x;
    const float* yr = &g_y[(size_t)row * Edim];
    float4 v = *(const float4*)(yr + t * 4);
    float s = v.x + v.y + v.z + v.w;
    float ss = v.x * v.x + v.y * v.y + v.z * v.z + v.w * v.w;
#pragma unroll
    for (int o = 16; o; o >>= 1) {
        s += __shfl_down_sync(0xffffffffu, s, o);
        ss += __shfl_down_sync(0xffffffffu, ss, o);
    }
    __shared__ float sh_s[8], sh_ss[8];
    int w = t >> 5, ln = t & 31;
    if (ln == 0) { sh_s[w] = s; sh_ss[w] = ss; }
    __syncthreads();
    if (t == 0) {
        float a = 0.f, b2 = 0.f;
#pragma unroll
        for (int i = 0; i < 8; i++) { a += sh_s[i]; b2 += sh_ss[i]; }
        sh_s[0] = a; sh_ss[0] = b2;
    }
    __syncthreads();
    float mu = sh_s[0] * (1.0f / Edim);
    float var = sh_ss[0] * (1.0f / Edim) - mu * mu;
    float rstd = rsqrtf(var + 1e-5f);
    float4 g = *(const float4*)(gamma + t * 4);
    float4 bb = *(const float4*)(beta + t * 4);
    float4 o;
    o.x = g.x * (v.x - mu) * rstd + bb.x;
    o.y = g.y * (v.y - mu) * rstd + bb.y;
    o.z = g.z * (v.z - mu) * rstd + bb.z;
    o.w = g.w * (v.w - mu) * rstd + bb.w;
    *(float4*)(out + (size_t)row * Edim + t * 4) = o;
}

// ---------------- launch ------------------------------------------------------
extern "C" void kernel_launch(void* const* d_in, const int* in_sizes, int n_in,
                              void* d_out, int out_size)
{
    const float* x     = (const float*)d_in[0];
    const float* Wq    = (const float*)d_in[1];
    const float* bq    = (const float*)d_in[2];
    const float* Wk    = (const float*)d_in[3];
    const float* bk    = (const float*)d_in[4];
    const float* Wv    = (const float*)d_in[5];
    const float* bv    = (const float*)d_in[6];
    const float* Wo    = (const float*)d_in[7];
    const float* bo    = (const float*)d_in[8];
    const float* gamma = (const float*)d_in[9];
    const float* beta  = (const float*)d_in[10];
    float* out = (float*)d_out;

    cudaFuncSetAttribute(p7_gemm_kernel<0>, cudaFuncAttributeMaxDynamicSharedMemorySize, GSMB);
    cudaFuncSetAttribute(p7_gemm_kernel<1>, cudaFuncAttributeMaxDynamicSharedMemorySize, GSMB);

    dim3 qkv_grid(Edim / 128, BL / 128, 3);
    dim3 o_grid(Edim / 128, BL / 128, 1);
    dim3 wgrid(Edim * Edim / (256 * 8), 4);

    p7_split_x_kernel<<<BL * Edim / (256 * 8), 256>>>(x);
    p7_split_w_kernel<<<wgrid, 256>>>(Wq, Wk, Wv, Wo);

    // fused q/k/v GEMM (one launch, 3072 blocks: fewer partial waves)
    p7_gemm_kernel<0><<<qkv_grid, 256, GSMB>>>(bq, bk, bv, nullptr);

    p7_chunk_stats_kernel<<<NCHUNKS, 512>>>();
    p7_scan_kernel<<<Bdim * Hn, 256>>>();
    p7_chunk_out_kernel<<<NCHUNKS * 2, 128>>>();

    p7_gemm_kernel<1><<<o_grid, 256, GSMB>>>(bo, nullptr, nullptr, x);   // y

    p7_ln_kernel<<<BL, 256>>>(gamma, beta, out);
}

// round 15
// speedup vs baseline: 1.1340x; 1.0867x over previous
#include <cuda_runtime.h>
#include <cuda_fp16.h>
#include <mma.h>
#include <math.h>
#include <stdint.h>

using namespace nvcuda;

#define Bdim 2
#define Lq 8192
#define Edim 1024
#define Hn 16
#define Dh 64
#define Cch 256
#define Nch (Lq / Cch)            // 32
#define BL (Bdim * Lq)            // 16384
#define NCHUNKS (Bdim * Hn * Nch) // 1024

// ---------------- scratch (device globals: no allocation allowed) ----------
__device__ float g_q[BL * Edim];
__device__ float g_k[BL * Edim];
__device__ float g_v[BL * Edim];
__device__ float g_y[BL * Edim];
__device__ float g_Sc[NCHUNKS * Dh * Dh];
__device__ float g_Sp[NCHUNKS * Dh * Dh];
__device__ float g_zc[NCHUNKS * Dh];
__device__ float g_zp[NCHUNKS * Dh];

// fp16 hi/lo operands (referenced only from device code)
__device__ __half g_xh[BL * Edim];
__device__ __half g_xl[BL * Edim];
__device__ __half g_ath[BL * Edim];
__device__ __half g_atl[BL * Edim];
__device__ __half g_wh[4][Edim * Edim];
__device__ __half g_wl[4][Edim * Edim];

// ============================ helpers =======================================
__device__ __forceinline__ uint32_t p8_smem_u32(const void* p) {
    uint32_t a;
    asm("{ .reg .u64 t; cvta.to.shared.u64 t, %1; cvt.u32.u64 %0, t; }"
        : "=r"(a) : "l"(p));
    return a;
}

#define CP_ASYNC_16(dst, src) \
    asm volatile("cp.async.cg.shared.global [%0], [%1], 16;" \
        :: "r"(dst), "l"(src))
#define CP_ASYNC_COMMIT() asm volatile("cp.async.commit_group;" ::: "memory")
#define CP_ASYNC_WAIT_1() asm volatile("cp.async.wait_group 1;" ::: "memory")
#define CP_ASYNC_WAIT_0() asm volatile("cp.async.wait_group 0;" ::: "memory")

__device__ __forceinline__ void p8_split1(float v, __half& h, __half& l) {
    h = __float2half_rn(v);
    l = __float2half_rn(__fsub_rn(v, __half2float(h)));
}

// ============================ split kernels =================================
__global__ void __launch_bounds__(256) p8_split_x_kernel(const float* __restrict__ x)
{
    size_t i = ((size_t)blockIdx.x * 256 + threadIdx.x) * 8;
    float4 v0 = *(const float4*)(x + i);
    float4 v1 = *(const float4*)(x + i + 4);
    float a[8] = {v0.x, v0.y, v0.z, v0.w, v1.x, v1.y, v1.z, v1.w};
    __half2 h[4], l[4];
#pragma unroll
    for (int j = 0; j < 4; j++) {
        __half hx, hy, lx, ly;
        p8_split1(a[2 * j], hx, lx);
        p8_split1(a[2 * j + 1], hy, ly);
        h[j] = __halves2half2(hx, hy);
        l[j] = __halves2half2(lx, ly);
    }
    *(float4*)(g_xh + i) = *(float4*)h;
    *(float4*)(g_xl + i) = *(float4*)l;
}

__global__ void __launch_bounds__(256) p8_split_w_kernel(
    const float* __restrict__ W0, const float* __restrict__ W1,
    const float* __restrict__ W2, const float* __restrict__ W3)
{
    int z = blockIdx.y;
    const float* W = (z == 0) ? W0 : (z == 1) ? W1 : (z == 2) ? W2 : W3;
    size_t i = ((size_t)blockIdx.x * 256 + threadIdx.x) * 8;
    float4 v0 = *(const float4*)(W + i);
    float4 v1 = *(const float4*)(W + i + 4);
    float a[8] = {v0.x, v0.y, v0.z, v0.w, v1.x, v1.y, v1.z, v1.w};
    __half2 h[4], l[4];
#pragma unroll
    for (int j = 0; j < 4; j++) {
        __half hx, hy, lx, ly;
        p8_split1(a[2 * j], hx, lx);
        p8_split1(a[2 * j + 1], hy, ly);
        h[j] = __halves2half2(hx, hy);
        l[j] = __halves2half2(lx, ly);
    }
    *(float4*)(&g_wh[z][0] + i) = *(float4*)h;
    *(float4*)(&g_wl[z][0] + i) = *(float4*)l;
}

// ============================ pure-FP16x3 WMMA GEMM (proven) ================
// MODE 0: fused qkv — blockIdx.z = widx (0:q phi, 1:k phi, 2:v none)
// MODE 1: output GEMM — widx=3, A = attn halves, +resid
#define NKTp (Edim / 16)
#define LDAH 24
#define LDBH 136
#define AH_O 0
#define AL_O (128 * LDAH)
#define BH_O (2 * 128 * LDAH)
#define BL_O (BH_O + 16 * LDBH)
#define STG_H (2 * 128 * LDAH + 2 * 16 * LDBH)
#define GSMB 65536

template <int MODE>
__global__ void __launch_bounds__(256, 2) p8_gemm_kernel(
    const float* __restrict__ bias0, const float* __restrict__ bias1,
    const float* __restrict__ bias2, const float* __restrict__ resid)
{
    extern __shared__ __half smh[];
    uint32_t sbase = p8_smem_u32(smh);
    int tid = threadIdx.x;
    int lane = tid & 31, wid = tid >> 5;

    int widx = (MODE == 0) ? blockIdx.z : 3;
    const __half* Ahg = (MODE == 0) ? &g_xh[0] : &g_ath[0];
    const __half* Alg = (MODE == 0) ? &g_xl[0] : &g_atl[0];
    const __half* Bhg = &g_wh[widx][0];
    const __half* Blg = &g_wl[widx][0];
    float* Cout;
    const float* bias;
    if (MODE == 0) {
        Cout = (widx == 0) ? &g_q[0] : (widx == 1) ? &g_k[0] : &g_v[0];
        bias = (widx == 0) ? bias0 : (widx == 1) ? bias1 : bias2;
    } else {
        Cout = &g_y[0];
        bias = bias0;
    }

    int bm = blockIdx.y * 128;
    int bn = blockIdx.x * 128;

    int arow = tid >> 1, acol = (tid & 1) * 8;
    int brow = tid >> 4, bcol = (tid & 15) * 8;
    const __half* gAh = Ahg + (size_t)(bm + arow) * Edim + acol;
    const __half* gAl = Alg + (size_t)(bm + arow) * Edim + acol;
    const __half* gBh = Bhg + (size_t)brow * Edim + bn + bcol;
    const __half* gBl = Blg + (size_t)brow * Edim + bn + bcol;
    uint32_t a_dst = (uint32_t)(arow * LDAH + acol) * 2;
    uint32_t b_dst = (uint32_t)(brow * LDBH + bcol) * 2;

#define ISSUE_LOADS(kt, stg) do {                                          \
    uint32_t s0 = sbase + (uint32_t)(stg) * (STG_H * 2);                   \
    size_t ao = (size_t)(kt) * 16;                                         \
    size_t bo = (size_t)(kt) * 16 * Edim;                                  \
    CP_ASYNC_16(s0 + AH_O * 2 + a_dst, gAh + ao);                          \
    CP_ASYNC_16(s0 + AL_O * 2 + a_dst, gAl + ao);                          \
    CP_ASYNC_16(s0 + BH_O * 2 + b_dst, gBh + bo);                          \
    CP_ASYNC_16(s0 + BL_O * 2 + b_dst, gBl + bo);                          \
    CP_ASYNC_COMMIT();                                                      \
} while (0)

    int Mb = (wid & 1) * 64;
    int Nb = (wid >> 1) * 32;

    wmma::fragment<wmma::accumulator, 16, 16, 16, float> acc[4][2];
#pragma unroll
    for (int mt = 0; mt < 4; mt++)
#pragma unroll
        for (int nt = 0; nt < 2; nt++) wmma::fill_fragment(acc[mt][nt], 0.0f);

    ISSUE_LOADS(0, 0);

    for (int kt = 0; kt < NKTp; kt++) {
        if (kt + 1 < NKTp) {
            ISSUE_LOADS(kt + 1, (kt + 1) & 1);
            CP_ASYNC_WAIT_1();
        } else {
            CP_ASYNC_WAIT_0();
        }
        __syncthreads();

        const __half* st = smh + (uint32_t)(kt & 1) * STG_H;
#pragma unroll
        for (int nt = 0; nt < 2; nt++) {
            wmma::fragment<wmma::matrix_b, 16, 16, 16, __half, wmma::row_major> fbh, fbl;
            wmma::load_matrix_sync(fbh, st + BH_O + Nb + nt * 16, LDBH);
            wmma::load_matrix_sync(fbl, st + BL_O + Nb + nt * 16, LDBH);
#pragma unroll
            for (int mt = 0; mt < 4; mt++) {
                wmma::fragment<wmma::matrix_a, 16, 16, 16, __half, wmma::row_major> fah, fal;
                wmma::load_matrix_sync(fah, st + AH_O + (Mb + mt * 16) * LDAH, LDAH);
                wmma::load_matrix_sync(fal, st + AL_O + (Mb + mt * 16) * LDAH, LDAH);
                wmma::mma_sync(acc[mt][nt], fah, fbl, acc[mt][nt]);
                wmma::mma_sync(acc[mt][nt], fal, fbh, acc[mt][nt]);
                wmma::mma_sync(acc[mt][nt], fah, fbh, acc[mt][nt]);
            }
        }
        __syncthreads();
    }

    float* wst = (float*)smh + wid * (64 * 32);
#pragma unroll
    for (int mt = 0; mt < 4; mt++)
#pragma unroll
        for (int nt = 0; nt < 2; nt++)
            wmma::store_matrix_sync(wst + mt * 16 * 32 + nt * 16, acc[mt][nt],
                                    32, wmma::mem_row_major);
    __syncwarp();

    bool do_phi = (MODE == 0) && (widx != 2);
    for (int e = lane; e < 64 * 8; e += 32) {
        int r = e >> 3, cb = (e & 7) * 4;
        float4 v = *(float4*)(wst + r * 32 + cb);
        int grow = bm + Mb + r;
        int gcol = bn + Nb + cb;
        float4 bb = *(const float4*)&bias[gcol];
        v.x += bb.x; v.y += bb.y; v.z += bb.z; v.w += bb.w;
        if (do_phi) {
            v.x = v.x > 0.f ? v.x + 1.f : expf(v.x);
            v.y = v.y > 0.f ? v.y + 1.f : expf(v.y);
            v.z = v.z > 0.f ? v.z + 1.f : expf(v.z);
            v.w = v.w > 0.f ? v.w + 1.f : expf(v.w);
        }
        if (MODE == 1) {
            float4 xr = *(const float4*)&resid[(size_t)grow * Edim + gcol];
            v.x += xr.x; v.y += xr.y; v.z += xr.z; v.w += xr.w;
        }
        *(float4*)&Cout[(size_t)grow * Edim + gcol] = v;
    }
#undef ISSUE_LOADS
}

// ---------------- per-chunk KV stats via WMMA --------------------------------
// S[d][e] = sum_s k[s][d] * v[s][e]  — A = k tile col-major, B = v row-major.
// fp16x3 compensated. z[d] = sum_s (kh+kl)[s][d].
#define LDK 72      // halfs per row (64 + 8 pad)
__global__ void __launch_bounds__(256) p8_chunk_stats_kernel()
{
    __shared__ __half kh[64 * LDK], kl[64 * LDK];
    __shared__ __half vh[64 * LDK], vl[64 * LDK];
    __shared__ float zs[4][64];

    int blk = blockIdx.x;
    int n = blk % Nch;
    int h = (blk / Nch) % Hn;
    int b = blk / (Nch * Hn);
    int rowbase = b * Lq + n * Cch;
    int colbase = h * Dh;
    int t = threadIdx.x;
    int wid = t >> 5;

    // conversion mapping: thread -> (row r, 16-col chunk c)
    int cr = t >> 2;
    int cc = (t & 3) * 16;

    // z mapping: thread t sums quarter sq of s for dim d
    int zd = t & 63;
    int zq = t >> 6;
    float zacc = 0.f;

    // warp tiling for 64x64 output: m-tile = wid>>1 (x16), n-base = (wid&1)*32
    int m0 = (wid >> 1) * 16;
    int n0 = (wid & 1) * 32;

    wmma::fragment<wmma::accumulator, 16, 16, 16, float> acc[2];
    wmma::fill_fragment(acc[0], 0.0f);
    wmma::fill_fragment(acc[1], 0.0f);

    for (int st = 0; st < Cch; st += 64) {
        // ---- convert k,v 64x64 f32 -> fp16 hi/lo in smem ----
        {
            size_t gofs = (size_t)(rowbase + st + cr) * Edim + colbase + cc;
            const float* kp = &g_k[gofs];
            const float* vp = &g_v[gofs];
            __half hbuf[16], lbuf[16];
#pragma unroll
            for (int j = 0; j < 16; j++) p8_split1(kp[j], hbuf[j], lbuf[j]);
            *(float4*)(kh + cr * LDK + cc) = *(float4*)hbuf;
            *(float4*)(kh + cr * LDK + cc + 8) = *(float4*)(hbuf + 8);
            *(float4*)(kl + cr * LDK + cc) = *(float4*)lbuf;
            *(float4*)(kl + cr * LDK + cc + 8) = *(float4*)(lbuf + 8);
#pragma unroll
            for (int j = 0; j < 16; j++) p8_split1(vp[j], hbuf[j], lbuf[j]);
            *(float4*)(vh + cr * LDK + cc) = *(float4*)hbuf;
            *(float4*)(vh + cr * LDK + cc + 8) = *(float4*)(hbuf + 8);
            *(float4*)(vl + cr * LDK + cc) = *(float4*)lbuf;
            *(float4*)(vl + cr * LDK + cc + 8) = *(float4*)(lbuf + 8);
        }
        __syncthreads();

        // ---- z partial: quarter zq sums s in [zq*16, zq*16+16) for dim zd ----
#pragma unroll
        for (int s = 0; s < 16; s++) {
            int srow = zq * 16 + s;
            zacc += __half2float(kh[srow * LDK + zd]) + __half2float(kl[srow * LDK + zd]);
        }

        // ---- mma: 4 ksteps over s ----
#pragma unroll
        for (int ks = 0; ks < 4; ks++) {
            int s0 = ks * 16;
            wmma::fragment<wmma::matrix_a, 16, 16, 16, __half, wmma::col_major> fah, fal;
            wmma::load_matrix_sync(fah, kh + m0 + s0 * LDK, LDK);
            wmma::load_matrix_sync(fal, kl + m0 + s0 * LDK, LDK);
#pragma unroll
            for (int j = 0; j < 2; j++) {
                wmma::fragment<wmma::matrix_b, 16, 16, 16, __half, wmma::row_major> fbh, fbl;
                wmma::load_matrix_sync(fbh, vh + s0 * LDK + n0 + j * 16, LDK);
                wmma::load_matrix_sync(fbl, vl + s0 * LDK + n0 + j * 16, LDK);
                wmma::mma_sync(acc[j], fah, fbl, acc[j]);
                wmma::mma_sync(acc[j], fal, fbh, acc[j]);
                wmma::mma_sync(acc[j], fah, fbh, acc[j]);
            }
        }
        __syncthreads();
    }

    // ---- write S and z ----
    float* Sb = &g_Sc[(size_t)blk * (Dh * Dh)];
    wmma::store_matrix_sync(Sb + m0 * 64 + n0, acc[0], 64, wmma::mem_row_major);
    wmma::store_matrix_sync(Sb + m0 * 64 + n0 + 16, acc[1], 64, wmma::mem_row_major);

    zs[zq][zd] = zacc;
    __syncthreads();
    if (t < 64)
        g_zc[blk * Dh + t] = zs[0][t] + zs[1][t] + zs[2][t] + zs[3][t];
}

// ---------------- exclusive prefix scan over chunks per (b,h) ---------------
__global__ void __launch_bounds__(256) p8_scan_kernel()
{
    int bh = blockIdx.x;
    int t = threadIdx.x;
    float run[16];
#pragma unroll
    for (int i = 0; i < 16; i++) run[i] = 0.f;
    float zrun = 0.f;

    for (int n = 0; n < Nch; n++) {
        size_t base = ((size_t)bh * Nch + n) * (Dh * Dh);
#pragma unroll
        for (int i = 0; i < 16; i++) {
            int idx = t + i * 256;
            g_Sp[base + idx] = run[i];
            run[i] += g_Sc[base + idx];
        }
        if (t < Dh) {
            size_t zb = ((size_t)bh * Nch + n) * Dh + t;
            g_zp[zb] = zrun;
            zrun += g_zc[zb];
        }
    }
}

// ---------------- per-chunk attention output (proven) ------------------------
__global__ void __launch_bounds__(128) p8_chunk_out_kernel()
{
    __shared__ float ks[64][64];
    __shared__ float vs[64][64];
    int bid = blockIdx.x;
    int blk = bid >> 1;
    int rh = bid & 1;
    int n = blk % Nch;
    int h = (blk / Nch) % Hn;
    int b = blk / (Nch * Hn);
    int rowbase = b * Lq + n * Cch;
    int colbase = h * Dh;
    int t = threadIdx.x;
    int row = rh * 128 + t;

    const float* qrow = &g_q[(size_t)(rowbase + row) * Edim + colbase];

    float qv[64];
#pragma unroll
    for (int j = 0; j < 16; j++) {
        float4 qq = *(const float4*)(qrow + 4 * j);
        qv[4 * j + 0] = qq.x; qv[4 * j + 1] = qq.y;
        qv[4 * j + 2] = qq.z; qv[4 * j + 3] = qq.w;
    }

    float acc[64];
#pragma unroll
    for (int j = 0; j < 64; j++) acc[j] = 0.f;

    const float* Sb = &g_Sp[(size_t)blk * (Dh * Dh)];
    for (int d = 0; d < 64; d++) {
        float qd = __ldg(qrow + d);
        const float4* S4 = (const float4*)(Sb + d * 64);
#pragma unroll
        for (int j = 0; j < 16; j++) {
            float4 sv = __ldg(S4 + j);
            acc[4 * j + 0] += qd * sv.x;
            acc[4 * j + 1] += qd * sv.y;
            acc[4 * j + 2] += qd * sv.z;
            acc[4 * j + 3] += qd * sv.w;
        }
    }

    float den = 0.f;
    const float* zb = &g_zp[(size_t)blk * Dh];
#pragma unroll
    for (int j = 0; j < 16; j++) {
        den += qv[4 * j + 0] * __ldg(zb + 4 * j + 0);
        den += qv[4 * j + 1] * __ldg(zb + 4 * j + 1);
        den += qv[4 * j + 2] * __ldg(zb + 4 * j + 2);
        den += qv[4 * j + 3] * __ldg(zb + 4 * j + 3);
    }

    int st_limit = (rh + 1) * 128;
    for (int st = 0; st < st_limit; st += 64) {
        for (int i = t; i < 1024; i += 128) {
            int r = i >> 4, c4 = (i & 15) * 4;
            size_t gofs = (size_t)(rowbase + st + r) * Edim + colbase + c4;
            *(float4*)&ks[r][c4] = *(const float4*)&g_k[gofs];
            *(float4*)&vs[r][c4] = *(const float4*)&g_v[gofs];
        }
        __syncthreads();
        int smax = row - st + 1;
        if (smax > 64) smax = 64;
        for (int s = 0; s < smax; s++) {
            const float4* k4 = (const float4*)&ks[s][0];
            float dot = 0.f;
#pragma unroll
            for (int j = 0; j < 16; j++) {
                float4 kk = k4[j];
                dot += qv[4 * j + 0] * kk.x + qv[4 * j + 1] * kk.y
                     + qv[4 * j + 2] * kk.z + qv[4 * j + 3] * kk.w;
            }
            den += dot;
            const float4* v4 = (const float4*)&vs[s][0];
#pragma unroll
            for (int j = 0; j < 16; j++) {
                float4 vv = v4[j];
                acc[4 * j + 0] += dot * vv.x;
                acc[4 * j + 1] += dot * vv.y;
                acc[4 * j + 2] += dot * vv.z;
                acc[4 * j + 3] += dot * vv.w;
            }
        }
        __syncthreads();
    }

    float inv = 1.0f / (den + 1e-6f);
    size_t oofs = (size_t)(rowbase + row) * Edim + colbase;
#pragma unroll
    for (int j = 0; j < 16; j++) {
        float o0 = acc[4 * j + 0] * inv;
        float o1 = acc[4 * j + 1] * inv;
        float o2 = acc[4 * j + 2] * inv;
        float o3 = acc[4 * j + 3] * inv;
        __half h0, h1, h2, h3, l0, l1, l2, l3;
        p8_split1(o0, h0, l0);
        p8_split1(o1, h1, l1);
        p8_split1(o2, h2, l2);
        p8_split1(o3, h3, l3);
        __half2 hh[2] = {__halves2half2(h0, h1), __halves2half2(h2, h3)};
        __half2 ll[2] = {__halves2half2(l0, l1), __halves2half2(l2, l3)};
        *(float2*)(g_ath + oofs + 4 * j) = *(float2*)hh;
        *(float2*)(g_atl + oofs + 4 * j) = *(float2*)ll;
    }
}

// ---------------- LayerNorm --------------------------------------------------
__global__ void __launch_bounds__(256) p8_ln_kernel(
    const float* __restrict__ gamma, const float* __restrict__ beta,
    float* __restrict__ out)
{
    int row = blockIdx.x;
    int t = threadIdx.x;
    const float* yr = &g_y[(size_t)row * Edim];
    float4 v = *(const float4*)(yr + t * 4);
    float s = v.x + v.y + v.z + v.w;
    float ss = v.x * v.x + v.y * v.y + v.z * v.z + v.w * v.w;
#pragma unroll
    for (int o = 16; o; o >>= 1) {
        s += __shfl_down_sync(0xffffffffu, s, o);
        ss += __shfl_down_sync(0xffffffffu, ss, o);
    }
    __shared__ float sh_s[8], sh_ss[8];
    int w = t >> 5, ln = t & 31;
    if (ln == 0) { sh_s[w] = s; sh_ss[w] = ss; }
    __syncthreads();
    if (t == 0) {
        float a = 0.f, b2 = 0.f;
#pragma unroll
        for (int i = 0; i < 8; i++) { a += sh_s[i]; b2 += sh_ss[i]; }
        sh_s[0] = a; sh_ss[0] = b2;
    }
    __syncthreads();
    float mu = sh_s[0] * (1.0f / Edim);
    float var = sh_ss[0] * (1.0f / Edim) - mu * mu;
    float rstd = rsqrtf(var + 1e-5f);
    float4 g = *(const float4*)(gamma + t * 4);
    float4 bb = *(const float4*)(beta + t * 4);
    float4 o;
    o.x = g.x * (v.x - mu) * rstd + bb.x;
    o.y = g.y * (v.y - mu) * rstd + bb.y;
    o.z = g.z * (v.z - mu) * rstd + bb.z;
    o.w = g.w * (v.w - mu) * rstd + bb.w;
    *(float4*)(out + (size_t)row * Edim + t * 4) = o;
}

// ---------------- launch ------------------------------------------------------
extern "C" void kernel_launch(void* const* d_in, const int* in_sizes, int n_in,
                              void* d_out, int out_size)
{
    const float* x     = (const float*)d_in[0];
    const float* Wq    = (const float*)d_in[1];
    const float* bq    = (const float*)d_in[2];
    const float* Wk    = (const float*)d_in[3];
    const float* bk    = (const float*)d_in[4];
    const float* Wv    = (const float*)d_in[5];
    const float* bv    = (const float*)d_in[6];
    const float* Wo    = (const float*)d_in[7];
    const float* bo    = (const float*)d_in[8];
    const float* gamma = (const float*)d_in[9];
    const float* beta  = (const float*)d_in[10];
    float* out = (float*)d_out;

    cudaFuncSetAttribute(p8_gemm_kernel<0>, cudaFuncAttributeMaxDynamicSharedMemorySize, GSMB);
    cudaFuncSetAttribute(p8_gemm_kernel<1>, cudaFuncAttributeMaxDynamicSharedMemorySize, GSMB);

    dim3 qkv_grid(Edim / 128, BL / 128, 3);
    dim3 o_grid(Edim / 128, BL / 128, 1);
    dim3 wgrid(Edim * Edim / (256 * 8), 4);

    p8_split_x_kernel<<<BL * Edim / (256 * 8), 256>>>(x);
    p8_split_w_kernel<<<wgrid, 256>>>(Wq, Wk, Wv, Wo);

    p8_gemm_kernel<0><<<qkv_grid, 256, GSMB>>>(bq, bk, bv, nullptr);

    p8_chunk_stats_kernel<<<NCHUNKS, 256>>>();
    p8_scan_kernel<<<Bdim * Hn, 256>>>();
    p8_chunk_out_kernel<<<NCHUNKS * 2, 128>>>();

    p8_gemm_kernel<1><<<o_grid, 256, GSMB>>>(bo, nullptr, nullptr, x);

    p8_ln_kernel<<<BL, 256>>>(gamma, beta, out);
}

// round 16
// speedup vs baseline: 1.2839x; 1.1322x over previous
#include <cuda_runtime.h>
#include <cuda_fp16.h>
#include <mma.h>
#include <math.h>
#include <stdint.h>

using namespace nvcuda;

#define Bdim 2
#define Lq 8192
#define Edim 1024
#define Hn 16
#define Dh 64
#define Cch 256
#define Nch (Lq / Cch)            // 32
#define BL (Bdim * Lq)            // 16384
#define NCHUNKS (Bdim * Hn * Nch) // 1024

// ---------------- scratch (device globals: no allocation allowed) ----------
__device__ float g_q[BL * Edim];
__device__ float g_k[BL * Edim];
__device__ float g_v[BL * Edim];
__device__ float g_y[BL * Edim];
__device__ float g_Sc[NCHUNKS * Dh * Dh];
__device__ float g_Sp[NCHUNKS * Dh * Dh];
__device__ float g_zc[NCHUNKS * Dh];
__device__ float g_zp[NCHUNKS * Dh];

// fp16 hi/lo operands (referenced only from device code)
__device__ __half g_xh[BL * Edim];
__device__ __half g_xl[BL * Edim];
__device__ __half g_ath[BL * Edim];
__device__ __half g_atl[BL * Edim];
__device__ __half g_wh[4][Edim * Edim];
__device__ __half g_wl[4][Edim * Edim];

// ============================ helpers =======================================
__device__ __forceinline__ uint32_t p9_smem_u32(const void* p) {
    uint32_t a;
    asm("{ .reg .u64 t; cvta.to.shared.u64 t, %1; cvt.u32.u64 %0, t; }"
        : "=r"(a) : "l"(p));
    return a;
}

#define CP_ASYNC_16(dst, src) \
    asm volatile("cp.async.cg.shared.global [%0], [%1], 16;" \
        :: "r"(dst), "l"(src))
#define CP_ASYNC_COMMIT() asm volatile("cp.async.commit_group;" ::: "memory")
#define CP_ASYNC_WAIT_1() asm volatile("cp.async.wait_group 1;" ::: "memory")
#define CP_ASYNC_WAIT_0() asm volatile("cp.async.wait_group 0;" ::: "memory")

__device__ __forceinline__ void p9_split1(float v, __half& h, __half& l) {
    h = __float2half_rn(v);
    l = __float2half_rn(__fsub_rn(v, __half2float(h)));
}

// ============================ split kernels =================================
__global__ void __launch_bounds__(256) p9_split_x_kernel(const float* __restrict__ x)
{
    size_t i = ((size_t)blockIdx.x * 256 + threadIdx.x) * 8;
    float4 v0 = *(const float4*)(x + i);
    float4 v1 = *(const float4*)(x + i + 4);
    float a[8] = {v0.x, v0.y, v0.z, v0.w, v1.x, v1.y, v1.z, v1.w};
    __half2 h[4], l[4];
#pragma unroll
    for (int j = 0; j < 4; j++) {
        __half hx, hy, lx, ly;
        p9_split1(a[2 * j], hx, lx);
        p9_split1(a[2 * j + 1], hy, ly);
        h[j] = __halves2half2(hx, hy);
        l[j] = __halves2half2(lx, ly);
    }
    *(float4*)(g_xh + i) = *(float4*)h;
    *(float4*)(g_xl + i) = *(float4*)l;
}

__global__ void __launch_bounds__(256) p9_split_w_kernel(
    const float* __restrict__ W0, const float* __restrict__ W1,
    const float* __restrict__ W2, const float* __restrict__ W3)
{
    int z = blockIdx.y;
    const float* W = (z == 0) ? W0 : (z == 1) ? W1 : (z == 2) ? W2 : W3;
    size_t i = ((size_t)blockIdx.x * 256 + threadIdx.x) * 8;
    float4 v0 = *(const float4*)(W + i);
    float4 v1 = *(const float4*)(W + i + 4);
    float a[8] = {v0.x, v0.y, v0.z, v0.w, v1.x, v1.y, v1.z, v1.w};
    __half2 h[4], l[4];
#pragma unroll
    for (int j = 0; j < 4; j++) {
        __half hx, hy, lx, ly;
        p9_split1(a[2 * j], hx, lx);
        p9_split1(a[2 * j + 1], hy, ly);
        h[j] = __halves2half2(hx, hy);
        l[j] = __halves2half2(lx, ly);
    }
    *(float4*)(&g_wh[z][0] + i) = *(float4*)h;
    *(float4*)(&g_wl[z][0] + i) = *(float4*)l;
}

// ============================ pure-FP16x3 WMMA GEMM (proven) ================
#define NKTp (Edim / 16)
#define LDAH 24
#define LDBH 136
#define AH_O 0
#define AL_O (128 * LDAH)
#define BH_O (2 * 128 * LDAH)
#define BL_O (BH_O + 16 * LDBH)
#define STG_H (2 * 128 * LDAH + 2 * 16 * LDBH)
#define GSMB 65536

template <int MODE>
__global__ void __launch_bounds__(256, 2) p9_gemm_kernel(
    const float* __restrict__ bias0, const float* __restrict__ bias1,
    const float* __restrict__ bias2, const float* __restrict__ resid)
{
    extern __shared__ __half smh[];
    uint32_t sbase = p9_smem_u32(smh);
    int tid = threadIdx.x;
    int lane = tid & 31, wid = tid >> 5;

    int widx = (MODE == 0) ? blockIdx.z : 3;
    const __half* Ahg = (MODE == 0) ? &g_xh[0] : &g_ath[0];
    const __half* Alg = (MODE == 0) ? &g_xl[0] : &g_atl[0];
    const __half* Bhg = &g_wh[widx][0];
    const __half* Blg = &g_wl[widx][0];
    float* Cout;
    const float* bias;
    if (MODE == 0) {
        Cout = (widx == 0) ? &g_q[0] : (widx == 1) ? &g_k[0] : &g_v[0];
        bias = (widx == 0) ? bias0 : (widx == 1) ? bias1 : bias2;
    } else {
        Cout = &g_y[0];
        bias = bias0;
    }

    int bm = blockIdx.y * 128;
    int bn = blockIdx.x * 128;

    int arow = tid >> 1, acol = (tid & 1) * 8;
    int brow = tid >> 4, bcol = (tid & 15) * 8;
    const __half* gAh = Ahg + (size_t)(bm + arow) * Edim + acol;
    const __half* gAl = Alg + (size_t)(bm + arow) * Edim + acol;
    const __half* gBh = Bhg + (size_t)brow * Edim + bn + bcol;
    const __half* gBl = Blg + (size_t)brow * Edim + bn + bcol;
    uint32_t a_dst = (uint32_t)(arow * LDAH + acol) * 2;
    uint32_t b_dst = (uint32_t)(brow * LDBH + bcol) * 2;

#define ISSUE_LOADS(kt, stg) do {                                          \
    uint32_t s0 = sbase + (uint32_t)(stg) * (STG_H * 2);                   \
    size_t ao = (size_t)(kt) * 16;                                         \
    size_t bo = (size_t)(kt) * 16 * Edim;                                  \
    CP_ASYNC_16(s0 + AH_O * 2 + a_dst, gAh + ao);                          \
    CP_ASYNC_16(s0 + AL_O * 2 + a_dst, gAl + ao);                          \
    CP_ASYNC_16(s0 + BH_O * 2 + b_dst, gBh + bo);                          \
    CP_ASYNC_16(s0 + BL_O * 2 + b_dst, gBl + bo);                          \
    CP_ASYNC_COMMIT();                                                      \
} while (0)

    int Mb = (wid & 1) * 64;
    int Nb = (wid >> 1) * 32;

    wmma::fragment<wmma::accumulator, 16, 16, 16, float> acc[4][2];
#pragma unroll
    for (int mt = 0; mt < 4; mt++)
#pragma unroll
        for (int nt = 0; nt < 2; nt++) wmma::fill_fragment(acc[mt][nt], 0.0f);

    ISSUE_LOADS(0, 0);

    for (int kt = 0; kt < NKTp; kt++) {
        if (kt + 1 < NKTp) {
            ISSUE_LOADS(kt + 1, (kt + 1) & 1);
            CP_ASYNC_WAIT_1();
        } else {
            CP_ASYNC_WAIT_0();
        }
        __syncthreads();

        const __half* st = smh + (uint32_t)(kt & 1) * STG_H;
#pragma unroll
        for (int nt = 0; nt < 2; nt++) {
            wmma::fragment<wmma::matrix_b, 16, 16, 16, __half, wmma::row_major> fbh, fbl;
            wmma::load_matrix_sync(fbh, st + BH_O + Nb + nt * 16, LDBH);
            wmma::load_matrix_sync(fbl, st + BL_O + Nb + nt * 16, LDBH);
#pragma unroll
            for (int mt = 0; mt < 4; mt++) {
                wmma::fragment<wmma::matrix_a, 16, 16, 16, __half, wmma::row_major> fah, fal;
                wmma::load_matrix_sync(fah, st + AH_O + (Mb + mt * 16) * LDAH, LDAH);
                wmma::load_matrix_sync(fal, st + AL_O + (Mb + mt * 16) * LDAH, LDAH);
                wmma::mma_sync(acc[mt][nt], fah, fbl, acc[mt][nt]);
                wmma::mma_sync(acc[mt][nt], fal, fbh, acc[mt][nt]);
                wmma::mma_sync(acc[mt][nt], fah, fbh, acc[mt][nt]);
            }
        }
        __syncthreads();
    }

    float* wst = (float*)smh + wid * (64 * 32);
#pragma unroll
    for (int mt = 0; mt < 4; mt++)
#pragma unroll
        for (int nt = 0; nt < 2; nt++)
            wmma::store_matrix_sync(wst + mt * 16 * 32 + nt * 16, acc[mt][nt],
                                    32, wmma::mem_row_major);
    __syncwarp();

    bool do_phi = (MODE == 0) && (widx != 2);
    for (int e = lane; e < 64 * 8; e += 32) {
        int r = e >> 3, cb = (e & 7) * 4;
        float4 v = *(float4*)(wst + r * 32 + cb);
        int grow = bm + Mb + r;
        int gcol = bn + Nb + cb;
        float4 bb = *(const float4*)&bias[gcol];
        v.x += bb.x; v.y += bb.y; v.z += bb.z; v.w += bb.w;
        if (do_phi) {
            v.x = v.x > 0.f ? v.x + 1.f : expf(v.x);
            v.y = v.y > 0.f ? v.y + 1.f : expf(v.y);
            v.z = v.z > 0.f ? v.z + 1.f : expf(v.z);
            v.w = v.w > 0.f ? v.w + 1.f : expf(v.w);
        }
        if (MODE == 1) {
            float4 xr = *(const float4*)&resid[(size_t)grow * Edim + gcol];
            v.x += xr.x; v.y += xr.y; v.z += xr.z; v.w += xr.w;
        }
        *(float4*)&Cout[(size_t)grow * Edim + gcol] = v;
    }
#undef ISSUE_LOADS
}

// ---------------- per-chunk KV stats via WMMA (proven) -----------------------
#define LDK 72
__global__ void __launch_bounds__(256) p9_chunk_stats_kernel()
{
    __shared__ __half kh[64 * LDK], kl[64 * LDK];
    __shared__ __half vh[64 * LDK], vl[64 * LDK];
    __shared__ float zs[4][64];

    int blk = blockIdx.x;
    int n = blk % Nch;
    int h = (blk / Nch) % Hn;
    int b = blk / (Nch * Hn);
    int rowbase = b * Lq + n * Cch;
    int colbase = h * Dh;
    int t = threadIdx.x;
    int wid = t >> 5;

    int cr = t >> 2;
    int cc = (t & 3) * 16;
    int zd = t & 63;
    int zq = t >> 6;
    float zacc = 0.f;

    int m0 = (wid >> 1) * 16;
    int n0 = (wid & 1) * 32;

    wmma::fragment<wmma::accumulator, 16, 16, 16, float> acc[2];
    wmma::fill_fragment(acc[0], 0.0f);
    wmma::fill_fragment(acc[1], 0.0f);

    for (int st = 0; st < Cch; st += 64) {
        {
            size_t gofs = (size_t)(rowbase + st + cr) * Edim + colbase + cc;
            const float* kp = &g_k[gofs];
            const float* vp = &g_v[gofs];
            __half hbuf[16], lbuf[16];
#pragma unroll
            for (int j = 0; j < 16; j++) p9_split1(kp[j], hbuf[j], lbuf[j]);
            *(float4*)(kh + cr * LDK + cc) = *(float4*)hbuf;
            *(float4*)(kh + cr * LDK + cc + 8) = *(float4*)(hbuf + 8);
            *(float4*)(kl + cr * LDK + cc) = *(float4*)lbuf;
            *(float4*)(kl + cr * LDK + cc + 8) = *(float4*)(lbuf + 8);
#pragma unroll
            for (int j = 0; j < 16; j++) p9_split1(vp[j], hbuf[j], lbuf[j]);
            *(float4*)(vh + cr * LDK + cc) = *(float4*)hbuf;
            *(float4*)(vh + cr * LDK + cc + 8) = *(float4*)(hbuf + 8);
            *(float4*)(vl + cr * LDK + cc) = *(float4*)lbuf;
            *(float4*)(vl + cr * LDK + cc + 8) = *(float4*)(lbuf + 8);
        }
        __syncthreads();

#pragma unroll
        for (int s = 0; s < 16; s++) {
            int srow = zq * 16 + s;
            zacc += __half2float(kh[srow * LDK + zd]) + __half2float(kl[srow * LDK + zd]);
        }

#pragma unroll
        for (int ks = 0; ks < 4; ks++) {
            int s0 = ks * 16;
            wmma::fragment<wmma::matrix_a, 16, 16, 16, __half, wmma::col_major> fah, fal;
            wmma::load_matrix_sync(fah, kh + m0 + s0 * LDK, LDK);
            wmma::load_matrix_sync(fal, kl + m0 + s0 * LDK, LDK);
#pragma unroll
            for (int j = 0; j < 2; j++) {
                wmma::fragment<wmma::matrix_b, 16, 16, 16, __half, wmma::row_major> fbh, fbl;
                wmma::load_matrix_sync(fbh, vh + s0 * LDK + n0 + j * 16, LDK);
                wmma::load_matrix_sync(fbl, vl + s0 * LDK + n0 + j * 16, LDK);
                wmma::mma_sync(acc[j], fah, fbl, acc[j]);
                wmma::mma_sync(acc[j], fal, fbh, acc[j]);
                wmma::mma_sync(acc[j], fah, fbh, acc[j]);
            }
        }
        __syncthreads();
    }

    float* Sb = &g_Sc[(size_t)blk * (Dh * Dh)];
    wmma::store_matrix_sync(Sb + m0 * 64 + n0, acc[0], 64, wmma::mem_row_major);
    wmma::store_matrix_sync(Sb + m0 * 64 + n0 + 16, acc[1], 64, wmma::mem_row_major);

    zs[zq][zd] = zacc;
    __syncthreads();
    if (t < 64)
        g_zc[blk * Dh + t] = zs[0][t] + zs[1][t] + zs[2][t] + zs[3][t];
}

// ---------------- exclusive prefix scan over chunks per (b,h) ---------------
__global__ void __launch_bounds__(256) p9_scan_kernel()
{
    int bh = blockIdx.x;
    int t = threadIdx.x;
    float run[16];
#pragma unroll
    for (int i = 0; i < 16; i++) run[i] = 0.f;
    float zrun = 0.f;

    for (int n = 0; n < Nch; n++) {
        size_t base = ((size_t)bh * Nch + n) * (Dh * Dh);
#pragma unroll
        for (int i = 0; i < 16; i++) {
            int idx = t + i * 256;
            g_Sp[base + idx] = run[i];
            run[i] += g_Sc[base + idx];
        }
        if (t < Dh) {
            size_t zb = ((size_t)bh * Nch + n) * Dh + t;
            g_zp[zb] = zrun;
            zrun += g_zc[zb];
        }
    }
}

// ---------------- per-chunk attention output via WMMA ------------------------
// block = (chunk, row-half rh). 256 threads, 8 warps, warp = 16-row m-tile.
// acc_o = q@Sp ; per s-tile: scores = q@k^T (masked) ; acc_o += scores@v.
#define LDS32 68
// smem offsets in halfs:
#define O_QH 0
#define O_QL (128 * LDK)                 // 9216
#define O_KH (2 * 128 * LDK)             // 18432 (aliases Sp-hi in phase 2)
#define O_KL (O_KH + 64 * LDK)           // 23040
#define O_VH (O_KL + 64 * LDK)           // 27648
#define O_VL (O_VH + 64 * LDK)           // 32256
#define O_SH (O_VL + 64 * LDK)           // 36864
#define O_SL (O_SH + 128 * LDK)          // 46080
#define O_SC32 (O_SL + 128 * LDK)        // 55296 (float area, 128*LDS32 f32)
#define O_DEN (O_SC32 + 128 * LDS32 * 2) // halfs offset; 128 f32
#define O_QZ  (O_DEN + 256)              // 128 f32
#define O_DENP (O_QZ + 256)              // 256 f32
#define CO_SMH (O_DENP + 512)            // total halfs = 73728 -> 147456 B
#define CO_GSMB (CO_SMH * 2)

__global__ void __launch_bounds__(256) p9_chunk_out_kernel()
{
    extern __shared__ __half sm[];
    float* sc32 = (float*)(sm + O_SC32);
    float* den  = (float*)(sm + O_DEN);
    float* qz   = (float*)(sm + O_QZ);
    float* denp = (float*)(sm + O_DENP);

    int bid = blockIdx.x;
    int blk = bid >> 1;
    int rh = bid & 1;
    int n = blk % Nch;
    int h = (blk / Nch) % Hn;
    int b = blk / (Nch * Hn);
    int rowbase = b * Lq + n * Cch;
    int colbase = h * Dh;
    int t = threadIdx.x;
    int wid = t >> 5;
    int m0 = wid * 16;             // warp m-tile rows [m0, m0+16)

    // ---- init: convert q (128x64) and Sp (64x64, into KH/KL alias); qz ----
    {
        int qr = t >> 1, c0 = (t & 1) * 32;
        const float* qp = &g_q[(size_t)(rowbase + rh * 128 + qr) * Edim + colbase + c0];
        __half hb[32], lb[32];
#pragma unroll
        for (int j = 0; j < 32; j++) p9_split1(qp[j], hb[j], lb[j]);
#pragma unroll
        for (int j = 0; j < 4; j++) {
            *(float4*)(sm + O_QH + qr * LDK + c0 + j * 8) = *(float4*)(hb + j * 8);
            *(float4*)(sm + O_QL + qr * LDK + c0 + j * 8) = *(float4*)(lb + j * 8);
        }
        int cr = t >> 2, cc = (t & 3) * 16;
        const float* sp = &g_Sp[(size_t)blk * (Dh * Dh) + cr * 64 + cc];
        __half hb2[16], lb2[16];
#pragma unroll
        for (int j = 0; j < 16; j++) p9_split1(sp[j], hb2[j], lb2[j]);
        *(float4*)(sm + O_KH + cr * LDK + cc)     = *(float4*)hb2;
        *(float4*)(sm + O_KH + cr * LDK + cc + 8) = *(float4*)(hb2 + 8);
        *(float4*)(sm + O_KL + cr * LDK + cc)     = *(float4*)lb2;
        *(float4*)(sm + O_KL + cr * LDK + cc + 8) = *(float4*)(lb2 + 8);

        if (t < 128) {
            const float* qrow = &g_q[(size_t)(rowbase + rh * 128 + t) * Edim + colbase];
            const float* zb = &g_zp[(size_t)blk * Dh];
            float s = 0.f;
#pragma unroll
            for (int d = 0; d < 64; d++) s += __ldg(qrow + d) * __ldg(zb + d);
            qz[t] = s;
        }
    }
    __syncthreads();

    // ---- phase 2: acc_o = q @ Sp (3-pass compensated) ----
    wmma::fragment<wmma::accumulator, 16, 16, 16, float> acc_o[4];
#pragma unroll
    for (int nt = 0; nt < 4; nt++) wmma::fill_fragment(acc_o[nt], 0.0f);
#pragma unroll
    for (int ks = 0; ks < 4; ks++) {
        wmma::fragment<wmma::matrix_a, 16, 16, 16, __half, wmma::row_major> fah, fal;
        wmma::load_matrix_sync(fah, sm + O_QH + m0 * LDK + ks * 16, LDK);
        wmma::load_matrix_sync(fal, sm + O_QL + m0 * LDK + ks * 16, LDK);
#pragma unroll
        for (int nt = 0; nt < 4; nt++) {
            wmma::fragment<wmma::matrix_b, 16, 16, 16, __half, wmma::row_major> fbh, fbl;
            wmma::load_matrix_sync(fbh, sm + O_KH + ks * 16 * LDK + nt * 16, LDK);
            wmma::load_matrix_sync(fbl, sm + O_KL + ks * 16 * LDK + nt * 16, LDK);
            wmma::mma_sync(acc_o[nt], fah, fbl, acc_o[nt]);
            wmma::mma_sync(acc_o[nt], fal, fbh, acc_o[nt]);
            wmma::mma_sync(acc_o[nt], fah, fbh, acc_o[nt]);
        }
    }
    __syncthreads();   // Sp (KH/KL alias) free for k tiles

    // ---- intra-chunk tiles ----
    float rsum = 0.f;                    // masked-scores rowsum partial
    int tr = t >> 1, ch0 = (t & 1) * 32; // this thread's (row, 32-col half)
    int myrow = rh * 128 + tr;           // row within chunk

    int st_limit = (rh + 1) * 128;
    for (int st = 0; st < st_limit; st += 64) {
        // convert k, v tile (64x64)
        {
            int cr = t >> 2, cc = (t & 3) * 16;
            size_t gofs = (size_t)(rowbase + st + cr) * Edim + colbase + cc;
            const float* kp = &g_k[gofs];
            const float* vp = &g_v[gofs];
            __half hb[16], lb[16];
#pragma unroll
            for (int j = 0; j < 16; j++) p9_split1(kp[j], hb[j], lb[j]);
            *(float4*)(sm + O_KH + cr * LDK + cc)     = *(float4*)hb;
            *(float4*)(sm + O_KH + cr * LDK + cc + 8) = *(float4*)(hb + 8);
            *(float4*)(sm + O_KL + cr * LDK + cc)     = *(float4*)lb;
            *(float4*)(sm + O_KL + cr * LDK + cc + 8) = *(float4*)(lb + 8);
#pragma unroll
            for (int j = 0; j < 16; j++) p9_split1(vp[j], hb[j], lb[j]);
            *(float4*)(sm + O_VH + cr * LDK + cc)     = *(float4*)hb;
            *(float4*)(sm + O_VH + cr * LDK + cc + 8) = *(float4*)(hb + 8);
            *(float4*)(sm + O_VL + cr * LDK + cc)     = *(float4*)lb;
            *(float4*)(sm + O_VL + cr * LDK + cc + 8) = *(float4*)(lb + 8);
        }
        __syncthreads();

        // scores = q @ k^T  (B = k tile col-major)
        {
            wmma::fragment<wmma::accumulator, 16, 16, 16, float> acc_s[4];
#pragma unroll
            for (int nt = 0; nt < 4; nt++) wmma::fill_fragment(acc_s[nt], 0.0f);
#pragma unroll
            for (int ks = 0; ks < 4; ks++) {
                wmma::fragment<wmma::matrix_a, 16, 16, 16, __half, wmma::row_major> fah, fal;
                wmma::load_matrix_sync(fah, sm + O_QH + m0 * LDK + ks * 16, LDK);
                wmma::load_matrix_sync(fal, sm + O_QL + m0 * LDK + ks * 16, LDK);
#pragma unroll
                for (int nt = 0; nt < 4; nt++) {
                    wmma::fragment<wmma::matrix_b, 16, 16, 16, __half, wmma::col_major> fbh, fbl;
                    wmma::load_matrix_sync(fbh, sm + O_KH + (nt * 16) * LDK + ks * 16, LDK);
                    wmma::load_matrix_sync(fbl, sm + O_KL + (nt * 16) * LDK + ks * 16, LDK);
                    wmma::mma_sync(acc_s[nt], fah, fbl, acc_s[nt]);
                    wmma::mma_sync(acc_s[nt], fal, fbh, acc_s[nt]);
                    wmma::mma_sync(acc_s[nt], fah, fbh, acc_s[nt]);
                }
            }
#pragma unroll
            for (int nt = 0; nt < 4; nt++)
                wmma::store_matrix_sync(sc32 + m0 * LDS32 + nt * 16, acc_s[nt],
                                        LDS32, wmma::mem_row_major);
        }
        __syncthreads();

        // mask + rowsum + split scores -> SH/SL
        {
            const float* srow = sc32 + tr * LDS32 + ch0;
            __half hb[32], lb[32];
            float part = 0.f;
#pragma unroll
            for (int j = 0; j < 32; j++) {
                float v = srow[j];
                int sg = st + ch0 + j;
                v = (sg <= myrow) ? v : 0.f;
                part += v;
                p9_split1(v, hb[j], lb[j]);
            }
            rsum += part;
#pragma unroll
            for (int j = 0; j < 4; j++) {
                *(float4*)(sm + O_SH + tr * LDK + ch0 + j * 8) = *(float4*)(hb + j * 8);
                *(float4*)(sm + O_SL + tr * LDK + ch0 + j * 8) = *(float4*)(lb + j * 8);
            }
        }
        __syncthreads();

        // acc_o += scores @ v
#pragma unroll
        for (int ks = 0; ks < 4; ks++) {
            wmma::fragment<wmma::matrix_a, 16, 16, 16, __half, wmma::row_major> fah, fal;
            wmma::load_matrix_sync(fah, sm + O_SH + m0 * LDK + ks * 16, LDK);
            wmma::load_matrix_sync(fal, sm + O_SL + m0 * LDK + ks * 16, LDK);
#pragma unroll
            for (int nt = 0; nt < 4; nt++) {
                wmma::fragment<wmma::matrix_b, 16, 16, 16, __half, wmma::row_major> fbh, fbl;
                wmma::load_matrix_sync(fbh, sm + O_VH + ks * 16 * LDK + nt * 16, LDK);
                wmma::load_matrix_sync(fbl, sm + O_VL + ks * 16 * LDK + nt * 16, LDK);
                wmma::mma_sync(acc_o[nt], fah, fbl, acc_o[nt]);
                wmma::mma_sync(acc_o[nt], fal, fbh, acc_o[nt]);
                wmma::mma_sync(acc_o[nt], fah, fbh, acc_o[nt]);
            }
        }
        __syncthreads();   // k/v/sc32/SH/SL free for next tile
    }

    // ---- finalize den ----
    denp[t] = rsum;
    __syncthreads();
    if (t < 128) den[t] = qz[t] + denp[2 * t] + denp[2 * t + 1];

    // ---- write output: acc_o / (den+eps) as fp16 hi/lo ----
#pragma unroll
    for (int nt = 0; nt < 4; nt++)
        wmma::store_matrix_sync(sc32 + m0 * LDS32 + nt * 16, acc_o[nt],
                                LDS32, wmma::mem_row_major);
    __syncthreads();

    {
        float inv = 1.0f / (den[tr] + 1e-6f);
        const float* orow = sc32 + tr * LDS32 + ch0;
        size_t oofs = (size_t)(rowbase + rh * 128 + tr) * Edim + colbase + ch0;
        __half hb[32], lb[32];
#pragma unroll
        for (int j = 0; j < 32; j++) p9_split1(orow[j] * inv, hb[j], lb[j]);
#pragma unroll
        for (int j = 0; j < 4; j++) {
            *(float4*)(g_ath + oofs + j * 8) = *(float4*)(hb + j * 8);
            *(float4*)(g_atl + oofs + j * 8) = *(float4*)(lb + j * 8);
        }
    }
}

// ---------------- LayerNorm --------------------------------------------------
__global__ void __launch_bounds__(256) p9_ln_kernel(
    const float* __restrict__ gamma, const float* __restrict__ beta,
    float* __restrict__ out)
{
    int row = blockIdx.x;
    int t = threadIdx.x;
    const float* yr = &g_y[(size_t)row * Edim];
    float4 v = *(const float4*)(yr + t * 4);
    float s = v.x + v.y + v.z + v.w;
    float ss = v.x * v.x + v.y * v.y + v.z * v.z + v.w * v.w;
#pragma unroll
    for (int o = 16; o; o >>= 1) {
        s += __shfl_down_sync(0xffffffffu, s, o);
        ss += __shfl_down_sync(0xffffffffu, ss, o);
    }
    __shared__ float sh_s[8], sh_ss[8];
    int w = t >> 5, ln = t & 31;
    if (ln == 0) { sh_s[w] = s; sh_ss[w] = ss; }
    __syncthreads();
    if (t == 0) {
        float a = 0.f, b2 = 0.f;
#pragma unroll
        for (int i = 0; i < 8; i++) { a += sh_s[i]; b2 += sh_ss[i]; }
        sh_s[0] = a; sh_ss[0] = b2;
    }
    __syncthreads();
    float mu = sh_s[0] * (1.0f / Edim);
    float var = sh_ss[0] * (1.0f / Edim) - mu * mu;
    float rstd = rsqrtf(var + 1e-5f);
    float4 g = *(const float4*)(gamma + t * 4);
    float4 bb = *(const float4*)(beta + t * 4);
    float4 o;
    o.x = g.x * (v.x - mu) * rstd + bb.x;
    o.y = g.y * (v.y - mu) * rstd + bb.y;
    o.z = g.z * (v.z - mu) * rstd + bb.z;
    o.w = g.w * (v.w - mu) * rstd + bb.w;
    *(float4*)(out + (size_t)row * Edim + t * 4) = o;
}

// ---------------- launch ------------------------------------------------------
extern "C" void kernel_launch(void* const* d_in, const int* in_sizes, int n_in,
                              void* d_out, int out_size)
{
    const float* x     = (const float*)d_in[0];
    const float* Wq    = (const float*)d_in[1];
    const float* bq    = (const float*)d_in[2];
    const float* Wk    = (const float*)d_in[3];
    const float* bk    = (const float*)d_in[4];
    const float* Wv    = (const float*)d_in[5];
    const float* bv    = (const float*)d_in[6];
    const float* Wo    = (const float*)d_in[7];
    const float* bo    = (const float*)d_in[8];
    const float* gamma = (const float*)d_in[9];
    const float* beta  = (const float*)d_in[10];
    float* out = (float*)d_out;

    cudaFuncSetAttribute(p9_gemm_kernel<0>, cudaFuncAttributeMaxDynamicSharedMemorySize, GSMB);
    cudaFuncSetAttribute(p9_gemm_kernel<1>, cudaFuncAttributeMaxDynamicSharedMemorySize, GSMB);
    cudaFuncSetAttribute(p9_chunk_out_kernel, cudaFuncAttributeMaxDynamicSharedMemorySize, CO_GSMB);

    dim3 qkv_grid(Edim / 128, BL / 128, 3);
    dim3 o_grid(Edim / 128, BL / 128, 1);
    dim3 wgrid(Edim * Edim / (256 * 8), 4);

    p9_split_x_kernel<<<BL * Edim / (256 * 8), 256>>>(x);
    p9_split_w_kernel<<<wgrid, 256>>>(Wq, Wk, Wv, Wo);

    p9_gemm_kernel<0><<<qkv_grid, 256, GSMB>>>(bq, bk, bv, nullptr);

    p9_chunk_stats_kernel<<<NCHUNKS, 256>>>();
    p9_scan_kernel<<<Bdim * Hn, 256>>>();
    p9_chunk_out_kernel<<<NCHUNKS * 2, 256, CO_GSMB>>>();

    p9_gemm_kernel<1><<<o_grid, 256, GSMB>>>(bo, nullptr, nullptr, x);

    p9_ln_kernel<<<BL, 256>>>(gamma, beta, out);
}